// round 3
// baseline (speedup 1.0000x reference)
#include <cuda_runtime.h>
#include <math.h>

#define NNODES 100000
#define NEDGES 100000
#define D      128
#define NTYPES 14

// ---------------- static device scratch (no allocations allowed) ----------------
__device__ float g_feat[NNODES * D];
__device__ float g_res [NNODES * D];
__device__ float g_tmp [NNODES * D];
__device__ float g_H   [NNODES * D];

// ---------------- lin1: relu(nodes[:,off:off+2] @ W1.T + b1) ----------------
__global__ void lin1_kernel(const float* __restrict__ nodes, int off,
                            const float* __restrict__ W1, const float* __restrict__ b1,
                            float* __restrict__ out) {
    int idx = blockIdx.x * blockDim.x + threadIdx.x;
    if (idx >= NNODES * D) return;
    int n = idx >> 7;
    int j = idx & 127;
    float x0 = nodes[n * 8 + off];
    float x1 = nodes[n * 8 + off + 1];
    float v = fmaf(x0, W1[j * 2 + 0], fmaf(x1, W1[j * 2 + 1], b1[j]));
    out[idx] = fmaxf(v, 0.0f);
}

// ---------------- GEMM: C[n, c] = sum_k A[n,k] * W[c, k]  (W row stride = ldw) --------
#define GEMM_THREADS 128
#define TILE_ROWS    64
#define SA_STRIDE    129
#define SW_STRIDE    130
#define GEMM_SMEM    ((128 * SW_STRIDE + TILE_ROWS * SA_STRIDE) * 4)

__global__ void __launch_bounds__(GEMM_THREADS)
gemm128_kernel(const float* __restrict__ A, const float* __restrict__ W,
               int ldw, float* __restrict__ C, int nrows) {
    extern __shared__ float sm[];
    float* sW = sm;                      // [128][SW_STRIDE]
    float* sA = sm + 128 * SW_STRIDE;    // [64][SA_STRIDE]
    int tid = threadIdx.x;

    // stage W once per block
    for (int idx = tid; idx < 128 * 128; idx += GEMM_THREADS) {
        int c = idx >> 7;
        int k = idx & 127;
        sW[c * SW_STRIDE + k] = W[c * ldw + k];
    }

    int rg = tid & 7;   // row group: rows rg*8 .. rg*8+7
    int cg = tid >> 3;  // col group: cols cg*8 .. cg*8+7
    int ntiles = (nrows + TILE_ROWS - 1) / TILE_ROWS;

    for (int tile = blockIdx.x; tile < ntiles; tile += gridDim.x) {
        int base = tile * TILE_ROWS;
        __syncthreads();   // protects sW (1st iter) and sA reuse (later iters)
        for (int idx = tid; idx < TILE_ROWS * 128; idx += GEMM_THREADS) {
            int r = idx >> 7;
            int k = idx & 127;
            int n = base + r;
            sA[r * SA_STRIDE + k] = (n < nrows) ? A[n * D + k] : 0.0f;
        }
        __syncthreads();

        float acc[8][8];
        #pragma unroll
        for (int i = 0; i < 8; i++)
            #pragma unroll
            for (int j = 0; j < 8; j++) acc[i][j] = 0.0f;

        #pragma unroll 4
        for (int k = 0; k < 128; k++) {
            float a[8], w[8];
            #pragma unroll
            for (int i = 0; i < 8; i++) a[i] = sA[(rg * 8 + i) * SA_STRIDE + k];
            #pragma unroll
            for (int j = 0; j < 8; j++) w[j] = sW[(cg * 8 + j) * SW_STRIDE + k];
            #pragma unroll
            for (int i = 0; i < 8; i++)
                #pragma unroll
                for (int j = 0; j < 8; j++)
                    acc[i][j] = fmaf(a[i], w[j], acc[i][j]);
        }

        #pragma unroll
        for (int i = 0; i < 8; i++) {
            int n = base + rg * 8 + i;
            if (n < nrows) {
                float4 v0 = make_float4(acc[i][0], acc[i][1], acc[i][2], acc[i][3]);
                float4 v1 = make_float4(acc[i][4], acc[i][5], acc[i][6], acc[i][7]);
                float4* dst = reinterpret_cast<float4*>(C + n * D + cg * 8);
                dst[0] = v0;
                dst[1] = v1;
            }
        }
    }
}

// ---------------- scatter: temp[dst[e]] += H[src[e]]  (one warp per edge) ------------
__global__ void scatter_kernel(const float* __restrict__ H,
                               const int* __restrict__ indexes,
                               const int* __restrict__ mask, int t,
                               float* __restrict__ temp) {
    int gid = blockIdx.x * blockDim.x + threadIdx.x;
    int e = gid >> 5;
    int lane = gid & 31;
    if (e >= NEDGES) return;
    if (e >= __ldg(mask + t)) return;
    // indexes[e*28 + 2t] = dst, indexes[e*28 + 2t + 1] = src; 8B-aligned pair
    int2 di = __ldg(reinterpret_cast<const int2*>(indexes + e * 28 + 2 * t));
    int dst = di.x;
    int src = di.y;
    float4 v = __ldg(reinterpret_cast<const float4*>(H + (long)src * D + lane * 4));
    float* p = temp + (long)dst * D + lane * 4;
    asm volatile("red.global.add.v4.f32 [%0], {%1, %2, %3, %4};"
                 :: "l"(p), "f"(v.x), "f"(v.y), "f"(v.z), "f"(v.w)
                 : "memory");
}

// ---------------- GroupNorm(1 group) helpers ----------------
__device__ __forceinline__ float warp_sum(float v) {
    #pragma unroll
    for (int o = 16; o > 0; o >>= 1) v += __shfl_xor_sync(0xffffffffu, v, o);
    return v;
}

// out1 = maybe_relu( gn(in)*g+b  [+ resid] ); optionally duplicate into out2
__global__ void gn_kernel(const float* __restrict__ in,
                          const float* __restrict__ g, const float* __restrict__ b,
                          const float* __restrict__ resid,
                          float* __restrict__ out1, float* __restrict__ out2,
                          int do_relu) {
    int warp = (blockIdx.x * blockDim.x + threadIdx.x) >> 5;
    int lane = threadIdx.x & 31;
    if (warp >= NNODES) return;
    const float4 x = *reinterpret_cast<const float4*>(in + (long)warp * D + lane * 4);
    float s  = x.x + x.y + x.z + x.w;
    float ss = x.x * x.x + x.y * x.y + x.z * x.z + x.w * x.w;
    s  = warp_sum(s);
    ss = warp_sum(ss);
    float m   = s * (1.0f / 128.0f);
    float var = ss * (1.0f / 128.0f) - m * m;
    float inv = rsqrtf(var + 1e-5f);
    float4 gg = *reinterpret_cast<const float4*>(g + lane * 4);
    float4 bb = *reinterpret_cast<const float4*>(b + lane * 4);
    float4 y;
    y.x = fmaf((x.x - m) * inv, gg.x, bb.x);
    y.y = fmaf((x.y - m) * inv, gg.y, bb.y);
    y.z = fmaf((x.z - m) * inv, gg.z, bb.z);
    y.w = fmaf((x.w - m) * inv, gg.w, bb.w);
    if (resid) {
        float4 r = *reinterpret_cast<const float4*>(resid + (long)warp * D + lane * 4);
        y.x += r.x; y.y += r.y; y.z += r.z; y.w += r.w;
    }
    if (do_relu) {
        y.x = fmaxf(y.x, 0.0f); y.y = fmaxf(y.y, 0.0f);
        y.z = fmaxf(y.z, 0.0f); y.w = fmaxf(y.w, 0.0f);
    }
    *reinterpret_cast<float4*>(out1 + (long)warp * D + lane * 4) = y;
    if (out2)
        *reinterpret_cast<float4*>(out2 + (long)warp * D + lane * 4) = y;
}

// out = relu( gn(inA)*gA+bA + gn(inB)*gB+bB )
__global__ void gn2_kernel(const float* __restrict__ inA,
                           const float* __restrict__ gA, const float* __restrict__ bA,
                           const float* __restrict__ inB,
                           const float* __restrict__ gB, const float* __restrict__ bB,
                           float* __restrict__ out) {
    int warp = (blockIdx.x * blockDim.x + threadIdx.x) >> 5;
    int lane = threadIdx.x & 31;
    if (warp >= NNODES) return;
    const float4 xa = *reinterpret_cast<const float4*>(inA + (long)warp * D + lane * 4);
    const float4 xb = *reinterpret_cast<const float4*>(inB + (long)warp * D + lane * 4);
    float sa  = xa.x + xa.y + xa.z + xa.w;
    float ssa = xa.x * xa.x + xa.y * xa.y + xa.z * xa.z + xa.w * xa.w;
    float sb  = xb.x + xb.y + xb.z + xb.w;
    float ssb = xb.x * xb.x + xb.y * xb.y + xb.z * xb.z + xb.w * xb.w;
    sa = warp_sum(sa); ssa = warp_sum(ssa);
    sb = warp_sum(sb); ssb = warp_sum(ssb);
    float ma = sa * (1.0f / 128.0f);
    float mb = sb * (1.0f / 128.0f);
    float ia = rsqrtf(ssa * (1.0f / 128.0f) - ma * ma + 1e-5f);
    float ib = rsqrtf(ssb * (1.0f / 128.0f) - mb * mb + 1e-5f);
    float4 ga4 = *reinterpret_cast<const float4*>(gA + lane * 4);
    float4 ba4 = *reinterpret_cast<const float4*>(bA + lane * 4);
    float4 gb4 = *reinterpret_cast<const float4*>(gB + lane * 4);
    float4 bb4 = *reinterpret_cast<const float4*>(bB + lane * 4);
    float4 y;
    y.x = fmaf((xa.x - ma) * ia, ga4.x, ba4.x) + fmaf((xb.x - mb) * ib, gb4.x, bb4.x);
    y.y = fmaf((xa.y - ma) * ia, ga4.y, ba4.y) + fmaf((xb.y - mb) * ib, gb4.y, bb4.y);
    y.z = fmaf((xa.z - ma) * ia, ga4.z, ba4.z) + fmaf((xb.z - mb) * ib, gb4.z, bb4.z);
    y.w = fmaf((xa.w - ma) * ia, ga4.w, ba4.w) + fmaf((xb.w - mb) * ib, gb4.w, bb4.w);
    y.x = fmaxf(y.x, 0.0f); y.y = fmaxf(y.y, 0.0f);
    y.z = fmaxf(y.z, 0.0f); y.w = fmaxf(y.w, 0.0f);
    *reinterpret_cast<float4*>(out + (long)warp * D + lane * 4) = y;
}

// ---------------- rank-4 update: out[n,c] += nodes[n,4:8] . metaW[c,128:132] ---------
__global__ void rank4_kernel(const float* __restrict__ nodes,
                             const float* __restrict__ metaW,
                             float* __restrict__ out) {
    int idx = blockIdx.x * blockDim.x + threadIdx.x;
    if (idx >= NNODES * D) return;
    int n = idx >> 7;
    int c = idx & 127;
    const float* wr = metaW + c * 132 + 128;
    const float* nd = nodes + n * 8 + 4;
    float s = fmaf(nd[0], wr[0], fmaf(nd[1], wr[1], fmaf(nd[2], wr[2], nd[3] * wr[3])));
    out[idx] += s;
}

// ---------------- final output: [feat.ravel(), nodes[:,:2].ravel()] ----------------
__global__ void copy_out_kernel(const float* __restrict__ feat,
                                const float* __restrict__ nodes,
                                float* __restrict__ out) {
    int idx = blockIdx.x * blockDim.x + threadIdx.x;
    const int F = NNODES * D;
    if (idx < F) {
        out[idx] = feat[idx];
    } else if (idx < F + NNODES * 2) {
        int j = idx - F;
        int n = j >> 1;
        int c = j & 1;
        out[idx] = nodes[n * 8 + c];
    }
}

// ---------------- host launcher ----------------
extern "C" void kernel_launch(void* const* d_in, const int* in_sizes, int n_in,
                              void* d_out, int out_size) {
    const float* nodes   = (const float*)d_in[0];
    const int*   indexes = (const int*)  d_in[1];
    const int*   mask    = (const int*)  d_in[2];
    const float* in1_W   = (const float*)d_in[3];
    const float* in1_b   = (const float*)d_in[4];
    const float* in2_W   = (const float*)d_in[5];
    const float* in_g    = (const float*)d_in[6];
    const float* in_bg   = (const float*)d_in[7];
    const float* seg1_W  = (const float*)d_in[8];
    const float* seg1_b  = (const float*)d_in[9];
    const float* seg2_W  = (const float*)d_in[10];
    const float* seg_g   = (const float*)d_in[11];
    const float* seg_bg  = (const float*)d_in[12];
    const float* meta_W  = (const float*)d_in[13];
    const float* meta_g  = (const float*)d_in[14];
    const float* meta_bg = (const float*)d_in[15];
    const float* ctr_W   = (const float*)d_in[16];
    const float* edge_W  = (const float*)d_in[17];
    const float* norm_g  = (const float*)d_in[18];
    const float* norm_bg = (const float*)d_in[19];
    const float* ctr2_W  = (const float*)d_in[20];
    const float* ctr2_g  = (const float*)d_in[21];
    const float* ctr2_bg = (const float*)d_in[22];
    float* out = (float*)d_out;

    float *feat, *res, *tmp, *H;
    cudaGetSymbolAddress((void**)&feat, g_feat);
    cudaGetSymbolAddress((void**)&res,  g_res);
    cudaGetSymbolAddress((void**)&tmp,  g_tmp);
    cudaGetSymbolAddress((void**)&H,    g_H);

    cudaFuncSetAttribute(gemm128_kernel,
                         cudaFuncAttributeMaxDynamicSharedMemorySize, GEMM_SMEM);

    const int GEMM_GRID = 592;
    const int lin_grid  = (NNODES * D + 255) / 256;
    const int gn_grid   = (NNODES * 32 + 255) / 256;
    const int sc_grid   = (NEDGES * 32 + 255) / 256;

    // ---- init: input + seg branches ----
    lin1_kernel<<<lin_grid, 256>>>(nodes, 0, in1_W, in1_b, tmp);
    gemm128_kernel<<<GEMM_GRID, GEMM_THREADS, GEMM_SMEM>>>(tmp, in2_W, 128, H, NNODES);
    lin1_kernel<<<lin_grid, 256>>>(nodes, 2, seg1_W, seg1_b, tmp);
    gemm128_kernel<<<GEMM_GRID, GEMM_THREADS, GEMM_SMEM>>>(tmp, seg2_W, 128, res, NNODES);
    gn2_kernel<<<gn_grid, 256>>>(H, in_g, in_bg, res, seg_g, seg_bg, feat);

    // ---- meta: concat(feat, nodes[:,4:8]) @ meta_W.T -> GN -> relu ----
    gemm128_kernel<<<GEMM_GRID, GEMM_THREADS, GEMM_SMEM>>>(feat, meta_W, 132, tmp, NNODES);
    rank4_kernel<<<lin_grid, 256>>>(nodes, meta_W, tmp);
    gn_kernel<<<gn_grid, 256>>>(tmp, meta_g, meta_bg, nullptr, feat, res, 1); // res = feat

    // ---- 4 message-passing layers ----
    for (int i = 0; i < 4; i++) {
        gemm128_kernel<<<GEMM_GRID, GEMM_THREADS, GEMM_SMEM>>>(
            feat, ctr_W + (long)i * D * D, 128, tmp, NNODES);
        for (int t = 0; t < NTYPES; t++) {
            gemm128_kernel<<<GEMM_GRID, GEMM_THREADS, GEMM_SMEM>>>(
                feat, edge_W + ((long)(i * NTYPES + t)) * D * D, 128, H, NNODES);
            scatter_kernel<<<sc_grid, 256>>>(H, indexes, mask, t, tmp);
        }
        gn_kernel<<<gn_grid, 256>>>(tmp, norm_g + i * D, norm_bg + i * D,
                                    nullptr, feat, nullptr, 1);
        gemm128_kernel<<<GEMM_GRID, GEMM_THREADS, GEMM_SMEM>>>(
            feat, ctr2_W + (long)i * D * D, 128, tmp, NNODES);
        gn_kernel<<<gn_grid, 256>>>(tmp, ctr2_g + i * D, ctr2_bg + i * D,
                                    res, feat, res, 1);   // feat = res = relu(gn+res)
    }

    // ---- outputs ----
    int total = NNODES * D + NNODES * 2;
    copy_out_kernel<<<(total + 255) / 256, 256>>>(feat, nodes, out);
}

// round 4
// speedup vs baseline: 1.8620x; 1.8620x over previous
#include <cuda_runtime.h>
#include <math.h>
#include <stdint.h>

#define NNODES 100000
#define NEDGES 100000
#define D      128
#define NTYPES 14

// ---------------- static device scratch (no allocations allowed) ----------------
__device__ float g_feat[NNODES * D];
__device__ float g_res [NNODES * D];
__device__ float g_tmp [NNODES * D];
__device__ float g_H   [NNODES * D];

// ---------------- lin1: relu(nodes[:,off:off+2] @ W1.T + b1) ----------------
__global__ void lin1_kernel(const float* __restrict__ nodes, int off,
                            const float* __restrict__ W1, const float* __restrict__ b1,
                            float* __restrict__ out) {
    int idx = blockIdx.x * blockDim.x + threadIdx.x;
    if (idx >= NNODES * D) return;
    int n = idx >> 7;
    int j = idx & 127;
    float x0 = nodes[n * 8 + off];
    float x1 = nodes[n * 8 + off + 1];
    float v = fmaf(x0, W1[j * 2 + 0], fmaf(x1, W1[j * 2 + 1], b1[j]));
    out[idx] = fmaxf(v, 0.0f);
}

// ---------------- tf32 helpers ----------------
__device__ __forceinline__ uint32_t f2tf32(float x) {
    uint32_t r;
    asm("cvt.rna.tf32.f32 %0, %1;" : "=r"(r) : "f"(x));
    return r;
}
__device__ __forceinline__ void split_tf32(float x, uint32_t& hi, uint32_t& lo) {
    hi = f2tf32(x);
    float rem = x - __uint_as_float(hi);
    lo = f2tf32(rem);
}
__device__ __forceinline__ void mma_tf32(float* d, const uint32_t* a, const uint32_t* b) {
    asm volatile(
        "mma.sync.aligned.m16n8k8.row.col.f32.tf32.tf32.f32 "
        "{%0,%1,%2,%3}, {%4,%5,%6,%7}, {%8,%9}, {%0,%1,%2,%3};"
        : "+f"(d[0]), "+f"(d[1]), "+f"(d[2]), "+f"(d[3])
        : "r"(a[0]), "r"(a[1]), "r"(a[2]), "r"(a[3]), "r"(b[0]), "r"(b[1]));
}

// ---------------- tensor-core GEMM: C[n,c] = sum_k A[n,k] * W[c,k]  (3xTF32) ----------
// Block: 256 threads = 8 warps. Each warp: 16-row strip x 128 cols.
// W (128x128, row stride ldw) staged in smem, stride 132 -> conflict-free b-frags.
#define TC_THREADS 256
#define TW_STRIDE  132
#define TC_SMEM    (128 * TW_STRIDE * 4)
#define TC_GRID    296

__global__ void __launch_bounds__(TC_THREADS, 2)
gemm_tc_kernel(const float* __restrict__ A, const float* __restrict__ W,
               int ldw, float* __restrict__ C, int nrows) {
    extern __shared__ float sW[];   // [128][TW_STRIDE]
    int tid = threadIdx.x;

    // stage W once per block
    for (int idx = tid; idx < 128 * 128; idx += TC_THREADS) {
        int c = idx >> 7;
        int k = idx & 127;
        sW[c * TW_STRIDE + k] = W[c * ldw + k];
    }
    __syncthreads();

    int wid  = tid >> 5;
    int lane = tid & 31;
    int qr = lane >> 2;   // 0..7
    int qk = lane & 3;    // 0..3

    int ntiles = (nrows + 127) / 128;
    for (int tile = blockIdx.x; tile < ntiles; tile += gridDim.x) {
        int rbase = tile * 128 + wid * 16;
        int r0 = rbase + qr;        // rows for a0/a2, c0/c1
        int r1 = rbase + qr + 8;    // rows for a1/a3, c2/c3
        bool v0 = r0 < nrows;
        bool v1 = r1 < nrows;
        const float* A0 = A + (long)r0 * D;
        const float* A1 = A + (long)r1 * D;

        float acc[16][4];
        #pragma unroll
        for (int nt = 0; nt < 16; nt++)
            #pragma unroll
            for (int j = 0; j < 4; j++) acc[nt][j] = 0.0f;

        #pragma unroll 1
        for (int kt = 0; kt < 16; kt++) {
            int k0 = kt * 8 + qk;
            float fa0 = v0 ? A0[k0]     : 0.0f;
            float fa1 = v1 ? A1[k0]     : 0.0f;
            float fa2 = v0 ? A0[k0 + 4] : 0.0f;
            float fa3 = v1 ? A1[k0 + 4] : 0.0f;
            uint32_t ah[4], al[4];
            split_tf32(fa0, ah[0], al[0]);
            split_tf32(fa1, ah[1], al[1]);
            split_tf32(fa2, ah[2], al[2]);
            split_tf32(fa3, ah[3], al[3]);

            const float* wb = sW + kt * 8 + qk;
            #pragma unroll
            for (int nt = 0; nt < 16; nt++) {
                float b0f = wb[(nt * 8 + qr) * TW_STRIDE];
                float b1f = wb[(nt * 8 + qr) * TW_STRIDE + 4];
                uint32_t bh[2], bl[2];
                split_tf32(b0f, bh[0], bl[0]);
                split_tf32(b1f, bh[1], bl[1]);
                mma_tf32(acc[nt], ah, bh);   // hi*hi
                mma_tf32(acc[nt], ah, bl);   // hi*lo
                mma_tf32(acc[nt], al, bh);   // lo*hi
            }
        }

        // store: c0/c1 -> (r0, 2*qk + nt*8), c2/c3 -> (r1, ...)
        #pragma unroll
        for (int nt = 0; nt < 16; nt++) {
            int col = nt * 8 + 2 * qk;
            if (v0)
                *reinterpret_cast<float2*>(C + (long)r0 * D + col) =
                    make_float2(acc[nt][0], acc[nt][1]);
            if (v1)
                *reinterpret_cast<float2*>(C + (long)r1 * D + col) =
                    make_float2(acc[nt][2], acc[nt][3]);
        }
    }
}

// ---------------- scatter: temp[dst[e]] += H[src[e]]  (one warp per edge) ------------
__global__ void scatter_kernel(const float* __restrict__ H,
                               const int* __restrict__ indexes,
                               const int* __restrict__ mask, int t,
                               float* __restrict__ temp) {
    int gid = blockIdx.x * blockDim.x + threadIdx.x;
    int e = gid >> 5;
    int lane = gid & 31;
    if (e >= NEDGES) return;
    if (e >= __ldg(mask + t)) return;
    int2 di = __ldg(reinterpret_cast<const int2*>(indexes + e * 28 + 2 * t));
    int dst = di.x;
    int src = di.y;
    float4 v = __ldg(reinterpret_cast<const float4*>(H + (long)src * D + lane * 4));
    float* p = temp + (long)dst * D + lane * 4;
    asm volatile("red.global.add.v4.f32 [%0], {%1, %2, %3, %4};"
                 :: "l"(p), "f"(v.x), "f"(v.y), "f"(v.z), "f"(v.w)
                 : "memory");
}

// ---------------- GroupNorm(1 group) helpers ----------------
__device__ __forceinline__ float warp_sum(float v) {
    #pragma unroll
    for (int o = 16; o > 0; o >>= 1) v += __shfl_xor_sync(0xffffffffu, v, o);
    return v;
}

// out1 = maybe_relu( gn(in)*g+b  [+ resid] ); optionally duplicate into out2
__global__ void gn_kernel(const float* __restrict__ in,
                          const float* __restrict__ g, const float* __restrict__ b,
                          const float* __restrict__ resid,
                          float* __restrict__ out1, float* __restrict__ out2,
                          int do_relu) {
    int warp = (blockIdx.x * blockDim.x + threadIdx.x) >> 5;
    int lane = threadIdx.x & 31;
    if (warp >= NNODES) return;
    const float4 x = *reinterpret_cast<const float4*>(in + (long)warp * D + lane * 4);
    float s  = x.x + x.y + x.z + x.w;
    float ss = x.x * x.x + x.y * x.y + x.z * x.z + x.w * x.w;
    s  = warp_sum(s);
    ss = warp_sum(ss);
    float m   = s * (1.0f / 128.0f);
    float var = ss * (1.0f / 128.0f) - m * m;
    float inv = rsqrtf(var + 1e-5f);
    float4 gg = *reinterpret_cast<const float4*>(g + lane * 4);
    float4 bb = *reinterpret_cast<const float4*>(b + lane * 4);
    float4 y;
    y.x = fmaf((x.x - m) * inv, gg.x, bb.x);
    y.y = fmaf((x.y - m) * inv, gg.y, bb.y);
    y.z = fmaf((x.z - m) * inv, gg.z, bb.z);
    y.w = fmaf((x.w - m) * inv, gg.w, bb.w);
    if (resid) {
        float4 r = *reinterpret_cast<const float4*>(resid + (long)warp * D + lane * 4);
        y.x += r.x; y.y += r.y; y.z += r.z; y.w += r.w;
    }
    if (do_relu) {
        y.x = fmaxf(y.x, 0.0f); y.y = fmaxf(y.y, 0.0f);
        y.z = fmaxf(y.z, 0.0f); y.w = fmaxf(y.w, 0.0f);
    }
    *reinterpret_cast<float4*>(out1 + (long)warp * D + lane * 4) = y;
    if (out2)
        *reinterpret_cast<float4*>(out2 + (long)warp * D + lane * 4) = y;
}

// out = relu( gn(inA)*gA+bA + gn(inB)*gB+bB )
__global__ void gn2_kernel(const float* __restrict__ inA,
                           const float* __restrict__ gA, const float* __restrict__ bA,
                           const float* __restrict__ inB,
                           const float* __restrict__ gB, const float* __restrict__ bB,
                           float* __restrict__ out) {
    int warp = (blockIdx.x * blockDim.x + threadIdx.x) >> 5;
    int lane = threadIdx.x & 31;
    if (warp >= NNODES) return;
    const float4 xa = *reinterpret_cast<const float4*>(inA + (long)warp * D + lane * 4);
    const float4 xb = *reinterpret_cast<const float4*>(inB + (long)warp * D + lane * 4);
    float sa  = xa.x + xa.y + xa.z + xa.w;
    float ssa = xa.x * xa.x + xa.y * xa.y + xa.z * xa.z + xa.w * xa.w;
    float sb  = xb.x + xb.y + xb.z + xb.w;
    float ssb = xb.x * xb.x + xb.y * xb.y + xb.z * xb.z + xb.w * xb.w;
    sa = warp_sum(sa); ssa = warp_sum(ssa);
    sb = warp_sum(sb); ssb = warp_sum(ssb);
    float ma = sa * (1.0f / 128.0f);
    float mb = sb * (1.0f / 128.0f);
    float ia = rsqrtf(ssa * (1.0f / 128.0f) - ma * ma + 1e-5f);
    float ib = rsqrtf(ssb * (1.0f / 128.0f) - mb * mb + 1e-5f);
    float4 ga4 = *reinterpret_cast<const float4*>(gA + lane * 4);
    float4 ba4 = *reinterpret_cast<const float4*>(bA + lane * 4);
    float4 gb4 = *reinterpret_cast<const float4*>(gB + lane * 4);
    float4 bb4 = *reinterpret_cast<const float4*>(bB + lane * 4);
    float4 y;
    y.x = fmaf((xa.x - ma) * ia, ga4.x, ba4.x) + fmaf((xb.x - mb) * ib, gb4.x, bb4.x);
    y.y = fmaf((xa.y - ma) * ia, ga4.y, ba4.y) + fmaf((xb.y - mb) * ib, gb4.y, bb4.y);
    y.z = fmaf((xa.z - ma) * ia, ga4.z, ba4.z) + fmaf((xb.z - mb) * ib, gb4.z, bb4.z);
    y.w = fmaf((xa.w - ma) * ia, ga4.w, ba4.w) + fmaf((xb.w - mb) * ib, gb4.w, bb4.w);
    y.x = fmaxf(y.x, 0.0f); y.y = fmaxf(y.y, 0.0f);
    y.z = fmaxf(y.z, 0.0f); y.w = fmaxf(y.w, 0.0f);
    *reinterpret_cast<float4*>(out + (long)warp * D + lane * 4) = y;
}

// ---------------- rank-4 update: out[n,c] += nodes[n,4:8] . metaW[c,128:132] ---------
__global__ void rank4_kernel(const float* __restrict__ nodes,
                             const float* __restrict__ metaW,
                             float* __restrict__ out) {
    int idx = blockIdx.x * blockDim.x + threadIdx.x;
    if (idx >= NNODES * D) return;
    int n = idx >> 7;
    int c = idx & 127;
    const float* wr = metaW + c * 132 + 128;
    const float* nd = nodes + n * 8 + 4;
    float s = fmaf(nd[0], wr[0], fmaf(nd[1], wr[1], fmaf(nd[2], wr[2], nd[3] * wr[3])));
    out[idx] += s;
}

// ---------------- final output: [feat.ravel(), nodes[:,:2].ravel()] ----------------
__global__ void copy_out_kernel(const float* __restrict__ feat,
                                const float* __restrict__ nodes,
                                float* __restrict__ out) {
    int idx = blockIdx.x * blockDim.x + threadIdx.x;
    const int F = NNODES * D;
    if (idx < F) {
        out[idx] = feat[idx];
    } else if (idx < F + NNODES * 2) {
        int j = idx - F;
        int n = j >> 1;
        int c = j & 1;
        out[idx] = nodes[n * 8 + c];
    }
}

// ---------------- host launcher ----------------
extern "C" void kernel_launch(void* const* d_in, const int* in_sizes, int n_in,
                              void* d_out, int out_size) {
    const float* nodes   = (const float*)d_in[0];
    const int*   indexes = (const int*)  d_in[1];
    const int*   mask    = (const int*)  d_in[2];
    const float* in1_W   = (const float*)d_in[3];
    const float* in1_b   = (const float*)d_in[4];
    const float* in2_W   = (const float*)d_in[5];
    const float* in_g    = (const float*)d_in[6];
    const float* in_bg   = (const float*)d_in[7];
    const float* seg1_W  = (const float*)d_in[8];
    const float* seg1_b  = (const float*)d_in[9];
    const float* seg2_W  = (const float*)d_in[10];
    const float* seg_g   = (const float*)d_in[11];
    const float* seg_bg  = (const float*)d_in[12];
    const float* meta_W  = (const float*)d_in[13];
    const float* meta_g  = (const float*)d_in[14];
    const float* meta_bg = (const float*)d_in[15];
    const float* ctr_W   = (const float*)d_in[16];
    const float* edge_W  = (const float*)d_in[17];
    const float* norm_g  = (const float*)d_in[18];
    const float* norm_bg = (const float*)d_in[19];
    const float* ctr2_W  = (const float*)d_in[20];
    const float* ctr2_g  = (const float*)d_in[21];
    const float* ctr2_bg = (const float*)d_in[22];
    float* out = (float*)d_out;

    float *feat, *res, *tmp, *H;
    cudaGetSymbolAddress((void**)&feat, g_feat);
    cudaGetSymbolAddress((void**)&res,  g_res);
    cudaGetSymbolAddress((void**)&tmp,  g_tmp);
    cudaGetSymbolAddress((void**)&H,    g_H);

    cudaFuncSetAttribute(gemm_tc_kernel,
                         cudaFuncAttributeMaxDynamicSharedMemorySize, TC_SMEM);

    const int lin_grid  = (NNODES * D + 255) / 256;
    const int gn_grid   = (NNODES * 32 + 255) / 256;
    const int sc_grid   = (NEDGES * 32 + 255) / 256;

    // ---- init: input + seg branches ----
    lin1_kernel<<<lin_grid, 256>>>(nodes, 0, in1_W, in1_b, tmp);
    gemm_tc_kernel<<<TC_GRID, TC_THREADS, TC_SMEM>>>(tmp, in2_W, 128, H, NNODES);
    lin1_kernel<<<lin_grid, 256>>>(nodes, 2, seg1_W, seg1_b, tmp);
    gemm_tc_kernel<<<TC_GRID, TC_THREADS, TC_SMEM>>>(tmp, seg2_W, 128, res, NNODES);
    gn2_kernel<<<gn_grid, 256>>>(H, in_g, in_bg, res, seg_g, seg_bg, feat);

    // ---- meta: concat(feat, nodes[:,4:8]) @ meta_W.T -> GN -> relu ----
    gemm_tc_kernel<<<TC_GRID, TC_THREADS, TC_SMEM>>>(feat, meta_W, 132, tmp, NNODES);
    rank4_kernel<<<lin_grid, 256>>>(nodes, meta_W, tmp);
    gn_kernel<<<gn_grid, 256>>>(tmp, meta_g, meta_bg, nullptr, feat, res, 1); // res = feat

    // ---- 4 message-passing layers ----
    for (int i = 0; i < 4; i++) {
        gemm_tc_kernel<<<TC_GRID, TC_THREADS, TC_SMEM>>>(
            feat, ctr_W + (long)i * D * D, 128, tmp, NNODES);
        for (int t = 0; t < NTYPES; t++) {
            gemm_tc_kernel<<<TC_GRID, TC_THREADS, TC_SMEM>>>(
                feat, edge_W + ((long)(i * NTYPES + t)) * D * D, 128, H, NNODES);
            scatter_kernel<<<sc_grid, 256>>>(H, indexes, mask, t, tmp);
        }
        gn_kernel<<<gn_grid, 256>>>(tmp, norm_g + i * D, norm_bg + i * D,
                                    nullptr, feat, nullptr, 1);
        gemm_tc_kernel<<<TC_GRID, TC_THREADS, TC_SMEM>>>(
            feat, ctr2_W + (long)i * D * D, 128, tmp, NNODES);
        gn_kernel<<<gn_grid, 256>>>(tmp, ctr2_g + i * D, ctr2_bg + i * D,
                                    res, feat, res, 1);   // feat = res = relu(gn+res)
    }

    // ---- outputs ----
    int total = NNODES * D + NNODES * 2;
    copy_out_kernel<<<(total + 255) / 256, 256>>>(feat, nodes, out);
}

// round 5
// speedup vs baseline: 2.0205x; 1.0852x over previous
#include <cuda_runtime.h>
#include <cuda_bf16.h>
#include <math.h>
#include <stdint.h>

#define NNODES 100000
#define NEDGES 100000
#define D      128
#define NTYPES 14
#define NSLOTS 67   // 0:in2  1:seg2  2:meta(128 cols of 132)  3..6:ctr  7..62:edge  63..66:ctr2

// ---------------- static device scratch (no allocations allowed) ----------------
__device__ float g_feat[NNODES * D];
__device__ float g_res [NNODES * D];
__device__ float g_tmp [NNODES * D];
__device__ float g_H   [NNODES * D];
__device__ uint32_t       g_Whi[NSLOTS * D * D];
__device__ __nv_bfloat16  g_Wlo[NSLOTS * D * D];

// ---------------- tf32 helpers ----------------
__device__ __forceinline__ uint32_t f2tf32(float x) {
    uint32_t r;
    asm("cvt.rna.tf32.f32 %0, %1;" : "=r"(r) : "f"(x));
    return r;
}
__device__ __forceinline__ void split_tf32(float x, uint32_t& hi, uint32_t& lo) {
    hi = f2tf32(x);
    float rem = x - __uint_as_float(hi);
    lo = f2tf32(rem);
}
__device__ __forceinline__ void mma_tf32(float* d, const uint32_t* a, const uint32_t* b) {
    asm volatile(
        "mma.sync.aligned.m16n8k8.row.col.f32.tf32.tf32.f32 "
        "{%0,%1,%2,%3}, {%4,%5,%6,%7}, {%8,%9}, {%0,%1,%2,%3};"
        : "+f"(d[0]), "+f"(d[1]), "+f"(d[2]), "+f"(d[3])
        : "r"(a[0]), "r"(a[1]), "r"(a[2]), "r"(a[3]), "r"(b[0]), "r"(b[1]));
}

// ---------------- pre-split all weight matrices: W -> (tf32 hi, bf16 lo) -------------
__global__ void split_w_kernel(const float* __restrict__ in2,
                               const float* __restrict__ seg2,
                               const float* __restrict__ meta,
                               const float* __restrict__ ctr,
                               const float* __restrict__ edge,
                               const float* __restrict__ ctr2,
                               uint32_t* __restrict__ Whi,
                               __nv_bfloat16* __restrict__ Wlo) {
    int idx = blockIdx.x * blockDim.x + threadIdx.x;
    if (idx >= NSLOTS * D * D) return;
    int slot = idx >> 14;          // /16384
    int r    = idx & 16383;
    float x;
    if      (slot == 0) x = in2[r];
    else if (slot == 1) x = seg2[r];
    else if (slot == 2) { int c = r >> 7, k = r & 127; x = meta[c * 132 + k]; }
    else if (slot < 7)  x = ctr [(slot - 3)  * 16384 + r];
    else if (slot < 63) x = edge[(slot - 7)  * 16384 + r];
    else                x = ctr2[(slot - 63) * 16384 + r];
    uint32_t hi = f2tf32(x);
    float rem = x - __uint_as_float(hi);
    Whi[idx] = hi;
    Wlo[idx] = __float2bfloat16_rn(rem);
}

// ---------------- lin1: relu(nodes[:,off:off+2] @ W1.T + b1) ----------------
__global__ void lin1_kernel(const float* __restrict__ nodes, int off,
                            const float* __restrict__ W1, const float* __restrict__ b1,
                            float* __restrict__ out) {
    int idx = blockIdx.x * blockDim.x + threadIdx.x;
    if (idx >= NNODES * D) return;
    int n = idx >> 7;
    int j = idx & 127;
    float x0 = nodes[n * 8 + off];
    float x1 = nodes[n * 8 + off + 1];
    float v = fmaf(x0, W1[j * 2 + 0], fmaf(x1, W1[j * 2 + 1], b1[j]));
    out[idx] = fmaxf(v, 0.0f);
}

// ---------------- tensor-core GEMM: C[n,c] = sum_k A[n,k] * W[c,k]  (3xTF32) ----------
// Block: 256 threads = 8 warps. Each warp: 16-row strip x 128 cols.
// Pre-split W staged in smem: hi as float (tf32 bits), lo as bf16. stride 132.
#define TC_THREADS 256
#define TW_STRIDE  132
#define TC_SMEM    (D * TW_STRIDE * 4 + D * TW_STRIDE * 2)
#define TC_GRID    296

__global__ void __launch_bounds__(TC_THREADS, 2)
gemm_tc_kernel(const float* __restrict__ A,
               const uint32_t* __restrict__ Whi,
               const __nv_bfloat16* __restrict__ Wlo,
               float* __restrict__ C, int nrows) {
    extern __shared__ char smraw[];
    uint32_t*      sWhi = reinterpret_cast<uint32_t*>(smraw);                 // [128][132]
    __nv_bfloat16* sWlo = reinterpret_cast<__nv_bfloat16*>(smraw + D * TW_STRIDE * 4);
    int tid = threadIdx.x;

    // stage pre-split W once per block
    for (int idx = tid; idx < D * D; idx += TC_THREADS) {
        int c = idx >> 7;
        int k = idx & 127;
        sWhi[c * TW_STRIDE + k] = Whi[idx];
        sWlo[c * TW_STRIDE + k] = Wlo[idx];
    }
    __syncthreads();

    int wid  = tid >> 5;
    int lane = tid & 31;
    int qr = lane >> 2;   // 0..7
    int qk = lane & 3;    // 0..3

    int ntiles = (nrows + 127) / 128;
    for (int tile = blockIdx.x; tile < ntiles; tile += gridDim.x) {
        int rbase = tile * 128 + wid * 16;
        int r0 = rbase + qr;        // rows for a0/a2, c0/c1
        int r1 = rbase + qr + 8;    // rows for a1/a3, c2/c3
        bool v0 = r0 < nrows;
        bool v1 = r1 < nrows;
        const float* A0 = A + (long)r0 * D;
        const float* A1 = A + (long)r1 * D;

        float acc[16][4];
        #pragma unroll
        for (int nt = 0; nt < 16; nt++)
            #pragma unroll
            for (int j = 0; j < 4; j++) acc[nt][j] = 0.0f;

        #pragma unroll 1
        for (int kt = 0; kt < 16; kt++) {
            int k0 = kt * 8 + qk;
            float fa0 = v0 ? A0[k0]     : 0.0f;
            float fa1 = v1 ? A1[k0]     : 0.0f;
            float fa2 = v0 ? A0[k0 + 4] : 0.0f;
            float fa3 = v1 ? A1[k0 + 4] : 0.0f;
            uint32_t ah[4], al[4];
            split_tf32(fa0, ah[0], al[0]);
            split_tf32(fa1, ah[1], al[1]);
            split_tf32(fa2, ah[2], al[2]);
            split_tf32(fa3, ah[3], al[3]);

            const uint32_t*      wh = sWhi + kt * 8 + qk;
            const __nv_bfloat16* wl = sWlo + kt * 8 + qk;
            #pragma unroll
            for (int nt = 0; nt < 16; nt++) {
                int roff = (nt * 8 + qr) * TW_STRIDE;
                uint32_t bh[2], bl[2];
                bh[0] = wh[roff];
                bh[1] = wh[roff + 4];
                bl[0] = ((uint32_t)__bfloat16_as_ushort(wl[roff]))     << 16;
                bl[1] = ((uint32_t)__bfloat16_as_ushort(wl[roff + 4])) << 16;
                mma_tf32(acc[nt], ah, bh);   // hi*hi
                mma_tf32(acc[nt], al, bh);   // lo*hi
                mma_tf32(acc[nt], ah, bl);   // hi*lo
            }
        }

        #pragma unroll
        for (int nt = 0; nt < 16; nt++) {
            int col = nt * 8 + 2 * qk;
            if (v0)
                *reinterpret_cast<float2*>(C + (long)r0 * D + col) =
                    make_float2(acc[nt][0], acc[nt][1]);
            if (v1)
                *reinterpret_cast<float2*>(C + (long)r1 * D + col) =
                    make_float2(acc[nt][2], acc[nt][3]);
        }
    }
}

// ---------------- scatter: temp[dst[e]] += H[src[e]]  (one warp per edge) ------------
__global__ void scatter_kernel(const float* __restrict__ H,
                               const int* __restrict__ indexes,
                               const int* __restrict__ mask, int t,
                               float* __restrict__ temp) {
    int gid = blockIdx.x * blockDim.x + threadIdx.x;
    int e = gid >> 5;
    int lane = gid & 31;
    if (e >= NEDGES) return;
    if (e >= __ldg(mask + t)) return;
    int2 di = __ldg(reinterpret_cast<const int2*>(indexes + e * 28 + 2 * t));
    int dst = di.x;
    int src = di.y;
    float4 v = __ldg(reinterpret_cast<const float4*>(H + (long)src * D + lane * 4));
    float* p = temp + (long)dst * D + lane * 4;
    asm volatile("red.global.add.v4.f32 [%0], {%1, %2, %3, %4};"
                 :: "l"(p), "f"(v.x), "f"(v.y), "f"(v.z), "f"(v.w)
                 : "memory");
}

// ---------------- GroupNorm(1 group) helpers ----------------
__device__ __forceinline__ float warp_sum(float v) {
    #pragma unroll
    for (int o = 16; o > 0; o >>= 1) v += __shfl_xor_sync(0xffffffffu, v, o);
    return v;
}

// out1 = maybe_relu( gn(in)*g+b  [+ resid] ); optionally duplicate into out2
__global__ void gn_kernel(const float* __restrict__ in,
                          const float* __restrict__ g, const float* __restrict__ b,
                          const float* __restrict__ resid,
                          float* __restrict__ out1, float* __restrict__ out2,
                          int do_relu) {
    int warp = (blockIdx.x * blockDim.x + threadIdx.x) >> 5;
    int lane = threadIdx.x & 31;
    if (warp >= NNODES) return;
    const float4 x = *reinterpret_cast<const float4*>(in + (long)warp * D + lane * 4);
    float s  = x.x + x.y + x.z + x.w;
    float ss = x.x * x.x + x.y * x.y + x.z * x.z + x.w * x.w;
    s  = warp_sum(s);
    ss = warp_sum(ss);
    float m   = s * (1.0f / 128.0f);
    float var = ss * (1.0f / 128.0f) - m * m;
    float inv = rsqrtf(var + 1e-5f);
    float4 gg = *reinterpret_cast<const float4*>(g + lane * 4);
    float4 bb = *reinterpret_cast<const float4*>(b + lane * 4);
    float4 y;
    y.x = fmaf((x.x - m) * inv, gg.x, bb.x);
    y.y = fmaf((x.y - m) * inv, gg.y, bb.y);
    y.z = fmaf((x.z - m) * inv, gg.z, bb.z);
    y.w = fmaf((x.w - m) * inv, gg.w, bb.w);
    if (resid) {
        float4 r = *reinterpret_cast<const float4*>(resid + (long)warp * D + lane * 4);
        y.x += r.x; y.y += r.y; y.z += r.z; y.w += r.w;
    }
    if (do_relu) {
        y.x = fmaxf(y.x, 0.0f); y.y = fmaxf(y.y, 0.0f);
        y.z = fmaxf(y.z, 0.0f); y.w = fmaxf(y.w, 0.0f);
    }
    *reinterpret_cast<float4*>(out1 + (long)warp * D + lane * 4) = y;
    if (out2)
        *reinterpret_cast<float4*>(out2 + (long)warp * D + lane * 4) = y;
}

// out = relu( gn(inA)*gA+bA + gn(inB)*gB+bB )
__global__ void gn2_kernel(const float* __restrict__ inA,
                           const float* __restrict__ gA, const float* __restrict__ bA,
                           const float* __restrict__ inB,
                           const float* __restrict__ gB, const float* __restrict__ bB,
                           float* __restrict__ out) {
    int warp = (blockIdx.x * blockDim.x + threadIdx.x) >> 5;
    int lane = threadIdx.x & 31;
    if (warp >= NNODES) return;
    const float4 xa = *reinterpret_cast<const float4*>(inA + (long)warp * D + lane * 4);
    const float4 xb = *reinterpret_cast<const float4*>(inB + (long)warp * D + lane * 4);
    float sa  = xa.x + xa.y + xa.z + xa.w;
    float ssa = xa.x * xa.x + xa.y * xa.y + xa.z * xa.z + xa.w * xa.w;
    float sb  = xb.x + xb.y + xb.z + xb.w;
    float ssb = xb.x * xb.x + xb.y * xb.y + xb.z * xb.z + xb.w * xb.w;
    sa = warp_sum(sa); ssa = warp_sum(ssa);
    sb = warp_sum(sb); ssb = warp_sum(ssb);
    float ma = sa * (1.0f / 128.0f);
    float mb = sb * (1.0f / 128.0f);
    float ia = rsqrtf(ssa * (1.0f / 128.0f) - ma * ma + 1e-5f);
    float ib = rsqrtf(ssb * (1.0f / 128.0f) - mb * mb + 1e-5f);
    float4 ga4 = *reinterpret_cast<const float4*>(gA + lane * 4);
    float4 ba4 = *reinterpret_cast<const float4*>(bA + lane * 4);
    float4 gb4 = *reinterpret_cast<const float4*>(gB + lane * 4);
    float4 bb4 = *reinterpret_cast<const float4*>(bB + lane * 4);
    float4 y;
    y.x = fmaf((xa.x - ma) * ia, ga4.x, ba4.x) + fmaf((xb.x - mb) * ib, gb4.x, bb4.x);
    y.y = fmaf((xa.y - ma) * ia, ga4.y, ba4.y) + fmaf((xb.y - mb) * ib, gb4.y, bb4.y);
    y.z = fmaf((xa.z - ma) * ia, ga4.z, ba4.z) + fmaf((xb.z - mb) * ib, gb4.z, bb4.z);
    y.w = fmaf((xa.w - ma) * ia, ga4.w, ba4.w) + fmaf((xb.w - mb) * ib, gb4.w, bb4.w);
    y.x = fmaxf(y.x, 0.0f); y.y = fmaxf(y.y, 0.0f);
    y.z = fmaxf(y.z, 0.0f); y.w = fmaxf(y.w, 0.0f);
    *reinterpret_cast<float4*>(out + (long)warp * D + lane * 4) = y;
}

// ---------------- rank-4 update: out[n,c] += nodes[n,4:8] . metaW[c,128:132] ---------
__global__ void rank4_kernel(const float* __restrict__ nodes,
                             const float* __restrict__ metaW,
                             float* __restrict__ out) {
    int idx = blockIdx.x * blockDim.x + threadIdx.x;
    if (idx >= NNODES * D) return;
    int n = idx >> 7;
    int c = idx & 127;
    const float* wr = metaW + c * 132 + 128;
    const float* nd = nodes + n * 8 + 4;
    float s = fmaf(nd[0], wr[0], fmaf(nd[1], wr[1], fmaf(nd[2], wr[2], nd[3] * wr[3])));
    out[idx] += s;
}

// ---------------- final output: [feat.ravel(), nodes[:,:2].ravel()] ----------------
__global__ void copy_out_kernel(const float* __restrict__ feat,
                                const float* __restrict__ nodes,
                                float* __restrict__ out) {
    int idx = blockIdx.x * blockDim.x + threadIdx.x;
    const int F = NNODES * D;
    if (idx < F) {
        out[idx] = feat[idx];
    } else if (idx < F + NNODES * 2) {
        int j = idx - F;
        int n = j >> 1;
        int c = j & 1;
        out[idx] = nodes[n * 8 + c];
    }
}

// ---------------- host launcher ----------------
extern "C" void kernel_launch(void* const* d_in, const int* in_sizes, int n_in,
                              void* d_out, int out_size) {
    const float* nodes   = (const float*)d_in[0];
    const int*   indexes = (const int*)  d_in[1];
    const int*   mask    = (const int*)  d_in[2];
    const float* in1_W   = (const float*)d_in[3];
    const float* in1_b   = (const float*)d_in[4];
    const float* in2_W   = (const float*)d_in[5];
    const float* in_g    = (const float*)d_in[6];
    const float* in_bg   = (const float*)d_in[7];
    const float* seg1_W  = (const float*)d_in[8];
    const float* seg1_b  = (const float*)d_in[9];
    const float* seg2_W  = (const float*)d_in[10];
    const float* seg_g   = (const float*)d_in[11];
    const float* seg_bg  = (const float*)d_in[12];
    const float* meta_W  = (const float*)d_in[13];
    const float* meta_g  = (const float*)d_in[14];
    const float* meta_bg = (const float*)d_in[15];
    const float* ctr_W   = (const float*)d_in[16];
    const float* edge_W  = (const float*)d_in[17];
    const float* norm_g  = (const float*)d_in[18];
    const float* norm_bg = (const float*)d_in[19];
    const float* ctr2_W  = (const float*)d_in[20];
    const float* ctr2_g  = (const float*)d_in[21];
    const float* ctr2_bg = (const float*)d_in[22];
    float* out = (float*)d_out;

    float *feat, *res, *tmp, *H;
    uint32_t* Whi;
    __nv_bfloat16* Wlo;
    cudaGetSymbolAddress((void**)&feat, g_feat);
    cudaGetSymbolAddress((void**)&res,  g_res);
    cudaGetSymbolAddress((void**)&tmp,  g_tmp);
    cudaGetSymbolAddress((void**)&H,    g_H);
    cudaGetSymbolAddress((void**)&Whi,  g_Whi);
    cudaGetSymbolAddress((void**)&Wlo,  g_Wlo);

    cudaFuncSetAttribute(gemm_tc_kernel,
                         cudaFuncAttributeMaxDynamicSharedMemorySize, TC_SMEM);

    const int lin_grid  = (NNODES * D + 255) / 256;
    const int gn_grid   = (NNODES * 32 + 255) / 256;
    const int sc_grid   = (NEDGES * 32 + 255) / 256;
    const int sw_grid   = (NSLOTS * D * D + 255) / 256;

    auto slotW = [&](int s) { return Whi + (long)s * D * D; };
    auto slotL = [&](int s) { return Wlo + (long)s * D * D; };

    // ---- pre-split weights ----
    split_w_kernel<<<sw_grid, 256>>>(in2_W, seg2_W, meta_W, ctr_W, edge_W, ctr2_W,
                                     Whi, Wlo);

    // ---- init: input + seg branches ----
    lin1_kernel<<<lin_grid, 256>>>(nodes, 0, in1_W, in1_b, tmp);
    gemm_tc_kernel<<<TC_GRID, TC_THREADS, TC_SMEM>>>(tmp, slotW(0), slotL(0), H, NNODES);
    lin1_kernel<<<lin_grid, 256>>>(nodes, 2, seg1_W, seg1_b, tmp);
    gemm_tc_kernel<<<TC_GRID, TC_THREADS, TC_SMEM>>>(tmp, slotW(1), slotL(1), res, NNODES);
    gn2_kernel<<<gn_grid, 256>>>(H, in_g, in_bg, res, seg_g, seg_bg, feat);

    // ---- meta: concat(feat, nodes[:,4:8]) @ meta_W.T -> GN -> relu ----
    gemm_tc_kernel<<<TC_GRID, TC_THREADS, TC_SMEM>>>(feat, slotW(2), slotL(2), tmp, NNODES);
    rank4_kernel<<<lin_grid, 256>>>(nodes, meta_W, tmp);
    gn_kernel<<<gn_grid, 256>>>(tmp, meta_g, meta_bg, nullptr, feat, res, 1); // res = feat

    // ---- 4 message-passing layers ----
    for (int i = 0; i < 4; i++) {
        gemm_tc_kernel<<<TC_GRID, TC_THREADS, TC_SMEM>>>(
            feat, slotW(3 + i), slotL(3 + i), tmp, NNODES);
        for (int t = 0; t < NTYPES; t++) {
            int s = 7 + i * NTYPES + t;
            gemm_tc_kernel<<<TC_GRID, TC_THREADS, TC_SMEM>>>(
                feat, slotW(s), slotL(s), H, NNODES);
            scatter_kernel<<<sc_grid, 256>>>(H, indexes, mask, t, tmp);
        }
        gn_kernel<<<gn_grid, 256>>>(tmp, norm_g + i * D, norm_bg + i * D,
                                    nullptr, feat, nullptr, 1);
        gemm_tc_kernel<<<TC_GRID, TC_THREADS, TC_SMEM>>>(
            feat, slotW(63 + i), slotL(63 + i), tmp, NNODES);
        gn_kernel<<<gn_grid, 256>>>(tmp, ctr2_g + i * D, ctr2_bg + i * D,
                                    res, feat, res, 1);   // feat = res = relu(gn+res)
    }

    // ---- outputs ----
    int total = NNODES * D + NNODES * 2;
    copy_out_kernel<<<(total + 255) / 256, 256>>>(feat, nodes, out);
}

// round 6
// speedup vs baseline: 2.7030x; 1.3378x over previous
#include <cuda_runtime.h>
#include <cuda_bf16.h>
#include <math.h>
#include <stdint.h>

#define NNODES 100000
#define NEDGES 100000
#define D      128
#define NPAIRS 64          // D/2 packed bf16x2 pairs per row
#define NTYPES 14
#define NSLOTS 67   // 0:in2 1:seg2 2:meta(first 128 cols) 3..6:ctr 7..62:edge 63..66:ctr2

// ---------------- static device scratch (no allocations allowed) ----------------
__device__ float    g_feat[NNODES * D];
__device__ float    g_res [NNODES * D];
__device__ float    g_tmp [NNODES * D];
__device__ float    g_H   [NNODES * D];
__device__ uint32_t g_Ahi [NNODES * NPAIRS];   // activations: packed bf16x2 hi
__device__ uint32_t g_Alo [NNODES * NPAIRS];   // activations: packed bf16x2 lo
__device__ uint32_t g_Whi [NSLOTS * D * NPAIRS];
__device__ uint32_t g_Wlo [NSLOTS * D * NPAIRS];

// ---------------- bf16 split helpers ----------------
// pack two floats into bf16x2: LOWER half <- e0, UPPER half <- e1
__device__ __forceinline__ uint32_t pack_bf16x2(float e0, float e1) {
    uint32_t r;
    asm("cvt.rn.bf16x2.f32 %0, %1, %2;" : "=r"(r) : "f"(e1), "f"(e0));
    return r;
}
// split a float pair into (hi packed, lo packed)
__device__ __forceinline__ void split_pair(float x0, float x1,
                                           uint32_t& hi, uint32_t& lo) {
    hi = pack_bf16x2(x0, x1);
    float h0 = __uint_as_float(hi << 16);
    float h1 = __uint_as_float(hi & 0xFFFF0000u);
    lo = pack_bf16x2(x0 - h0, x1 - h1);
}

__device__ __forceinline__ void mma_bf16(float* d, const uint32_t* a, const uint32_t* b) {
    asm volatile(
        "mma.sync.aligned.m16n8k16.row.col.f32.bf16.bf16.f32 "
        "{%0,%1,%2,%3}, {%4,%5,%6,%7}, {%8,%9}, {%0,%1,%2,%3};"
        : "+f"(d[0]), "+f"(d[1]), "+f"(d[2]), "+f"(d[3])
        : "r"(a[0]), "r"(a[1]), "r"(a[2]), "r"(a[3]), "r"(b[0]), "r"(b[1]));
}

// ---------------- pre-split all weight matrices into packed bf16x2 hi/lo -------------
__global__ void split_w_kernel(const float* __restrict__ in2,
                               const float* __restrict__ seg2,
                               const float* __restrict__ meta,
                               const float* __restrict__ ctr,
                               const float* __restrict__ edge,
                               const float* __restrict__ ctr2,
                               uint32_t* __restrict__ Whi,
                               uint32_t* __restrict__ Wlo) {
    int idx = blockIdx.x * blockDim.x + threadIdx.x;   // over NSLOTS*D*NPAIRS
    if (idx >= NSLOTS * D * NPAIRS) return;
    int slot = idx / (D * NPAIRS);
    int r    = idx - slot * (D * NPAIRS);   // c*64 + p
    int c    = r >> 6;
    int p    = r & 63;
    int k0 = 2 * p;
    float x0, x1;
    if      (slot == 0) { x0 = in2 [c * D + k0]; x1 = in2 [c * D + k0 + 1]; }
    else if (slot == 1) { x0 = seg2[c * D + k0]; x1 = seg2[c * D + k0 + 1]; }
    else if (slot == 2) { x0 = meta[c * 132 + k0]; x1 = meta[c * 132 + k0 + 1]; }
    else if (slot < 7)  { const float* w = ctr  + (long)(slot - 3)  * D * D;
                          x0 = w[c * D + k0]; x1 = w[c * D + k0 + 1]; }
    else if (slot < 63) { const float* w = edge + (long)(slot - 7)  * D * D;
                          x0 = w[c * D + k0]; x1 = w[c * D + k0 + 1]; }
    else                { const float* w = ctr2 + (long)(slot - 63) * D * D;
                          x0 = w[c * D + k0]; x1 = w[c * D + k0 + 1]; }
    uint32_t hi, lo;
    split_pair(x0, x1, hi, lo);
    Whi[idx] = hi;
    Wlo[idx] = lo;
}

// ---------------- lin1: relu(nodes[:,off:off+2] @ W1.T + b1) -> split output ---------
__global__ void lin1_kernel(const float* __restrict__ nodes, int off,
                            const float* __restrict__ W1, const float* __restrict__ b1,
                            uint32_t* __restrict__ Ahi, uint32_t* __restrict__ Alo) {
    int idx = blockIdx.x * blockDim.x + threadIdx.x;   // over NNODES*NPAIRS
    if (idx >= NNODES * NPAIRS) return;
    int n = idx >> 6;
    int p = idx & 63;
    int j0 = 2 * p;
    float x0 = nodes[n * 8 + off];
    float x1 = nodes[n * 8 + off + 1];
    float v0 = fmaxf(fmaf(x0, W1[j0 * 2],     fmaf(x1, W1[j0 * 2 + 1], b1[j0])),     0.0f);
    float v1 = fmaxf(fmaf(x0, W1[j0 * 2 + 2], fmaf(x1, W1[j0 * 2 + 3], b1[j0 + 1])), 0.0f);
    uint32_t hi, lo;
    split_pair(v0, v1, hi, lo);
    Ahi[idx] = hi;
    Alo[idx] = lo;
}

// ---------------- tensor-core GEMM: C[n,c] = sum_k A[n,k]*W[c,k]  (3xBF16 k16) -------
// Block 256 thr = 8 warps; warp = 32 rows x 64 cols (2 strips of 16 rows, nt=8).
// Block tile: 128 rows x 128 cols. W staged in smem as packed pairs, stride 68.
#define TC_THREADS 256
#define SW_STR     68
#define TC_SMEM    (2 * D * SW_STR * 4)
#define TC_GRID    296

__global__ void __launch_bounds__(TC_THREADS, 2)
gemm_tc_kernel(const uint32_t* __restrict__ Ahi, const uint32_t* __restrict__ Alo,
               const uint32_t* __restrict__ Whi, const uint32_t* __restrict__ Wlo,
               float* __restrict__ C, int nrows) {
    extern __shared__ uint32_t sm[];
    uint32_t* sWhi = sm;                 // [128][68]
    uint32_t* sWlo = sm + D * SW_STR;    // [128][68]
    int tid = threadIdx.x;

    for (int idx = tid; idx < D * NPAIRS; idx += TC_THREADS) {
        int c = idx >> 6;
        int p = idx & 63;
        sWhi[c * SW_STR + p] = Whi[idx];
        sWlo[c * SW_STR + p] = Wlo[idx];
    }
    __syncthreads();

    int wid  = tid >> 5;
    int lane = tid & 31;
    int rgrp = wid >> 1;        // 0..3 : 32-row group
    int cgrp = wid & 1;         // 0..1 : 64-col group
    int qr = lane >> 2;         // 0..7
    int qk = lane & 3;          // 0..3

    int ntiles = (nrows + 127) / 128;
    for (int tile = blockIdx.x; tile < ntiles; tile += gridDim.x) {
        int rbase = tile * 128 + rgrp * 32;
        int r00 = rbase + qr;          // strip 0 rows
        int r01 = rbase + qr + 8;
        int r10 = rbase + 16 + qr;     // strip 1 rows
        int r11 = rbase + 16 + qr + 8;
        bool v00 = r00 < nrows, v01 = r01 < nrows;
        bool v10 = r10 < nrows, v11 = r11 < nrows;

        float acc[2][8][4];
        #pragma unroll
        for (int s = 0; s < 2; s++)
            #pragma unroll
            for (int nt = 0; nt < 8; nt++)
                #pragma unroll
                for (int j = 0; j < 4; j++) acc[s][nt][j] = 0.0f;

        #pragma unroll
        for (int kt = 0; kt < 8; kt++) {
            int p0 = kt * 8 + qk;
            int p1 = p0 + 4;
            uint32_t ah0[4], al0[4], ah1[4], al1[4];
            ah0[0] = v00 ? Ahi[(long)r00 * NPAIRS + p0] : 0u;
            ah0[1] = v01 ? Ahi[(long)r01 * NPAIRS + p0] : 0u;
            ah0[2] = v00 ? Ahi[(long)r00 * NPAIRS + p1] : 0u;
            ah0[3] = v01 ? Ahi[(long)r01 * NPAIRS + p1] : 0u;
            al0[0] = v00 ? Alo[(long)r00 * NPAIRS + p0] : 0u;
            al0[1] = v01 ? Alo[(long)r01 * NPAIRS + p0] : 0u;
            al0[2] = v00 ? Alo[(long)r00 * NPAIRS + p1] : 0u;
            al0[3] = v01 ? Alo[(long)r01 * NPAIRS + p1] : 0u;
            ah1[0] = v10 ? Ahi[(long)r10 * NPAIRS + p0] : 0u;
            ah1[1] = v11 ? Ahi[(long)r11 * NPAIRS + p0] : 0u;
            ah1[2] = v10 ? Ahi[(long)r10 * NPAIRS + p1] : 0u;
            ah1[3] = v11 ? Ahi[(long)r11 * NPAIRS + p1] : 0u;
            al1[0] = v10 ? Alo[(long)r10 * NPAIRS + p0] : 0u;
            al1[1] = v11 ? Alo[(long)r11 * NPAIRS + p0] : 0u;
            al1[2] = v10 ? Alo[(long)r10 * NPAIRS + p1] : 0u;
            al1[3] = v11 ? Alo[(long)r11 * NPAIRS + p1] : 0u;

            #pragma unroll
            for (int nt = 0; nt < 8; nt++) {
                int n = cgrp * 64 + nt * 8 + qr;
                int off = n * SW_STR;
                uint32_t bh[2], bl[2];
                bh[0] = sWhi[off + p0];
                bh[1] = sWhi[off + p1];
                bl[0] = sWlo[off + p0];
                bl[1] = sWlo[off + p1];
                mma_bf16(acc[0][nt], ah0, bh);
                mma_bf16(acc[0][nt], al0, bh);
                mma_bf16(acc[0][nt], ah0, bl);
                mma_bf16(acc[1][nt], ah1, bh);
                mma_bf16(acc[1][nt], al1, bh);
                mma_bf16(acc[1][nt], ah1, bl);
            }
        }

        #pragma unroll
        for (int nt = 0; nt < 8; nt++) {
            int col = cgrp * 64 + nt * 8 + 2 * qk;
            if (v00) *reinterpret_cast<float2*>(C + (long)r00 * D + col) =
                         make_float2(acc[0][nt][0], acc[0][nt][1]);
            if (v01) *reinterpret_cast<float2*>(C + (long)r01 * D + col) =
                         make_float2(acc[0][nt][2], acc[0][nt][3]);
            if (v10) *reinterpret_cast<float2*>(C + (long)r10 * D + col) =
                         make_float2(acc[1][nt][0], acc[1][nt][1]);
            if (v11) *reinterpret_cast<float2*>(C + (long)r11 * D + col) =
                         make_float2(acc[1][nt][2], acc[1][nt][3]);
        }
    }
}

// ---------------- scatter: temp[dst[e]] += H[src[e]]  (one warp per edge) ------------
__global__ void scatter_kernel(const float* __restrict__ H,
                               const int* __restrict__ indexes,
                               const int* __restrict__ mask, int t,
                               float* __restrict__ temp) {
    int gid = blockIdx.x * blockDim.x + threadIdx.x;
    int e = gid >> 5;
    int lane = gid & 31;
    if (e >= NEDGES) return;
    if (e >= __ldg(mask + t)) return;
    int2 di = __ldg(reinterpret_cast<const int2*>(indexes + e * 28 + 2 * t));
    int dst = di.x;
    int src = di.y;
    float4 v = __ldg(reinterpret_cast<const float4*>(H + (long)src * D + lane * 4));
    float* p = temp + (long)dst * D + lane * 4;
    asm volatile("red.global.add.v4.f32 [%0], {%1, %2, %3, %4};"
                 :: "l"(p), "f"(v.x), "f"(v.y), "f"(v.z), "f"(v.w)
                 : "memory");
}

// ---------------- GroupNorm(1 group) helpers ----------------
__device__ __forceinline__ float warp_sum(float v) {
    #pragma unroll
    for (int o = 16; o > 0; o >>= 1) v += __shfl_xor_sync(0xffffffffu, v, o);
    return v;
}

__device__ __forceinline__ void store_split4(uint32_t* Ahi, uint32_t* Alo,
                                             int row, int lane, float4 y) {
    uint32_t h0, l0, h1, l1;
    split_pair(y.x, y.y, h0, l0);
    split_pair(y.z, y.w, h1, l1);
    *reinterpret_cast<uint2*>(Ahi + (long)row * NPAIRS + lane * 2) = make_uint2(h0, h1);
    *reinterpret_cast<uint2*>(Alo + (long)row * NPAIRS + lane * 2) = make_uint2(l0, l1);
}

// out1 = maybe_relu( gn(in)*g+b [+resid] ); optional dup to out2; optional split out
__global__ void gn_kernel(const float* __restrict__ in,
                          const float* __restrict__ g, const float* __restrict__ b,
                          const float* __restrict__ resid,
                          float* __restrict__ out1, float* __restrict__ out2,
                          uint32_t* __restrict__ Ahi, uint32_t* __restrict__ Alo,
                          int do_relu) {
    int warp = (blockIdx.x * blockDim.x + threadIdx.x) >> 5;
    int lane = threadIdx.x & 31;
    if (warp >= NNODES) return;
    const float4 x = *reinterpret_cast<const float4*>(in + (long)warp * D + lane * 4);
    float s  = x.x + x.y + x.z + x.w;
    float ss = x.x * x.x + x.y * x.y + x.z * x.z + x.w * x.w;
    s  = warp_sum(s);
    ss = warp_sum(ss);
    float m   = s * (1.0f / 128.0f);
    float var = ss * (1.0f / 128.0f) - m * m;
    float inv = rsqrtf(var + 1e-5f);
    float4 gg = *reinterpret_cast<const float4*>(g + lane * 4);
    float4 bb = *reinterpret_cast<const float4*>(b + lane * 4);
    float4 y;
    y.x = fmaf((x.x - m) * inv, gg.x, bb.x);
    y.y = fmaf((x.y - m) * inv, gg.y, bb.y);
    y.z = fmaf((x.z - m) * inv, gg.z, bb.z);
    y.w = fmaf((x.w - m) * inv, gg.w, bb.w);
    if (resid) {
        float4 r = *reinterpret_cast<const float4*>(resid + (long)warp * D + lane * 4);
        y.x += r.x; y.y += r.y; y.z += r.z; y.w += r.w;
    }
    if (do_relu) {
        y.x = fmaxf(y.x, 0.0f); y.y = fmaxf(y.y, 0.0f);
        y.z = fmaxf(y.z, 0.0f); y.w = fmaxf(y.w, 0.0f);
    }
    *reinterpret_cast<float4*>(out1 + (long)warp * D + lane * 4) = y;
    if (out2)
        *reinterpret_cast<float4*>(out2 + (long)warp * D + lane * 4) = y;
    if (Ahi) store_split4(Ahi, Alo, warp, lane, y);
}

// out = relu( gn(inA)*gA+bA + gn(inB)*gB+bB ), plus split output
__global__ void gn2_kernel(const float* __restrict__ inA,
                           const float* __restrict__ gA, const float* __restrict__ bA,
                           const float* __restrict__ inB,
                           const float* __restrict__ gB, const float* __restrict__ bB,
                           float* __restrict__ out,
                           uint32_t* __restrict__ Ahi, uint32_t* __restrict__ Alo) {
    int warp = (blockIdx.x * blockDim.x + threadIdx.x) >> 5;
    int lane = threadIdx.x & 31;
    if (warp >= NNODES) return;
    const float4 xa = *reinterpret_cast<const float4*>(inA + (long)warp * D + lane * 4);
    const float4 xb = *reinterpret_cast<const float4*>(inB + (long)warp * D + lane * 4);
    float sa  = xa.x + xa.y + xa.z + xa.w;
    float ssa = xa.x * xa.x + xa.y * xa.y + xa.z * xa.z + xa.w * xa.w;
    float sb  = xb.x + xb.y + xb.z + xb.w;
    float ssb = xb.x * xb.x + xb.y * xb.y + xb.z * xb.z + xb.w * xb.w;
    sa = warp_sum(sa); ssa = warp_sum(ssa);
    sb = warp_sum(sb); ssb = warp_sum(ssb);
    float ma = sa * (1.0f / 128.0f);
    float mb = sb * (1.0f / 128.0f);
    float ia = rsqrtf(ssa * (1.0f / 128.0f) - ma * ma + 1e-5f);
    float ib = rsqrtf(ssb * (1.0f / 128.0f) - mb * mb + 1e-5f);
    float4 ga4 = *reinterpret_cast<const float4*>(gA + lane * 4);
    float4 ba4 = *reinterpret_cast<const float4*>(bA + lane * 4);
    float4 gb4 = *reinterpret_cast<const float4*>(gB + lane * 4);
    float4 bb4 = *reinterpret_cast<const float4*>(bB + lane * 4);
    float4 y;
    y.x = fmaf((xa.x - ma) * ia, ga4.x, ba4.x) + fmaf((xb.x - mb) * ib, gb4.x, bb4.x);
    y.y = fmaf((xa.y - ma) * ia, ga4.y, ba4.y) + fmaf((xb.y - mb) * ib, gb4.y, bb4.y);
    y.z = fmaf((xa.z - ma) * ia, ga4.z, ba4.z) + fmaf((xb.z - mb) * ib, gb4.z, bb4.z);
    y.w = fmaf((xa.w - ma) * ia, ga4.w, ba4.w) + fmaf((xb.w - mb) * ib, gb4.w, bb4.w);
    y.x = fmaxf(y.x, 0.0f); y.y = fmaxf(y.y, 0.0f);
    y.z = fmaxf(y.z, 0.0f); y.w = fmaxf(y.w, 0.0f);
    *reinterpret_cast<float4*>(out + (long)warp * D + lane * 4) = y;
    store_split4(Ahi, Alo, warp, lane, y);
}

// ---------------- rank-4 update: out[n,c] += nodes[n,4:8] . metaW[c,128:132] ---------
__global__ void rank4_kernel(const float* __restrict__ nodes,
                             const float* __restrict__ metaW,
                             float* __restrict__ out) {
    int idx = blockIdx.x * blockDim.x + threadIdx.x;
    if (idx >= NNODES * D) return;
    int n = idx >> 7;
    int c = idx & 127;
    const float* wr = metaW + c * 132 + 128;
    const float* nd = nodes + n * 8 + 4;
    float s = fmaf(nd[0], wr[0], fmaf(nd[1], wr[1], fmaf(nd[2], wr[2], nd[3] * wr[3])));
    out[idx] += s;
}

// ---------------- final output: [feat.ravel(), nodes[:,:2].ravel()] ----------------
__global__ void copy_out_kernel(const float* __restrict__ feat,
                                const float* __restrict__ nodes,
                                float* __restrict__ out) {
    int idx = blockIdx.x * blockDim.x + threadIdx.x;
    const int F = NNODES * D;
    if (idx < F) {
        out[idx] = feat[idx];
    } else if (idx < F + NNODES * 2) {
        int j = idx - F;
        int n = j >> 1;
        int c = j & 1;
        out[idx] = nodes[n * 8 + c];
    }
}

// ---------------- host launcher ----------------
extern "C" void kernel_launch(void* const* d_in, const int* in_sizes, int n_in,
                              void* d_out, int out_size) {
    const float* nodes   = (const float*)d_in[0];
    const int*   indexes = (const int*)  d_in[1];
    const int*   mask    = (const int*)  d_in[2];
    const float* in1_W   = (const float*)d_in[3];
    const float* in1_b   = (const float*)d_in[4];
    const float* in2_W   = (const float*)d_in[5];
    const float* in_g    = (const float*)d_in[6];
    const float* in_bg   = (const float*)d_in[7];
    const float* seg1_W  = (const float*)d_in[8];
    const float* seg1_b  = (const float*)d_in[9];
    const float* seg2_W  = (const float*)d_in[10];
    const float* seg_g   = (const float*)d_in[11];
    const float* seg_bg  = (const float*)d_in[12];
    const float* meta_W  = (const float*)d_in[13];
    const float* meta_g  = (const float*)d_in[14];
    const float* meta_bg = (const float*)d_in[15];
    const float* ctr_W   = (const float*)d_in[16];
    const float* edge_W  = (const float*)d_in[17];
    const float* norm_g  = (const float*)d_in[18];
    const float* norm_bg = (const float*)d_in[19];
    const float* ctr2_W  = (const float*)d_in[20];
    const float* ctr2_g  = (const float*)d_in[21];
    const float* ctr2_bg = (const float*)d_in[22];
    float* out = (float*)d_out;

    float *feat, *res, *tmp, *H;
    uint32_t *Whi, *Wlo, *Ahi, *Alo;
    cudaGetSymbolAddress((void**)&feat, g_feat);
    cudaGetSymbolAddress((void**)&res,  g_res);
    cudaGetSymbolAddress((void**)&tmp,  g_tmp);
    cudaGetSymbolAddress((void**)&H,    g_H);
    cudaGetSymbolAddress((void**)&Whi,  g_Whi);
    cudaGetSymbolAddress((void**)&Wlo,  g_Wlo);
    cudaGetSymbolAddress((void**)&Ahi,  g_Ahi);
    cudaGetSymbolAddress((void**)&Alo,  g_Alo);

    cudaFuncSetAttribute(gemm_tc_kernel,
                         cudaFuncAttributeMaxDynamicSharedMemorySize, TC_SMEM);

    const int lin_grid  = (NNODES * NPAIRS + 255) / 256;
    const int gn_grid   = (NNODES * 32 + 255) / 256;
    const int sc_grid   = (NEDGES * 32 + 255) / 256;
    const int sw_grid   = (NSLOTS * D * NPAIRS + 255) / 256;
    const int r4_grid   = (NNODES * D + 255) / 256;

    auto sW = [&](int s) { return Whi + (long)s * D * NPAIRS; };
    auto sL = [&](int s) { return Wlo + (long)s * D * NPAIRS; };

    // ---- pre-split weights ----
    split_w_kernel<<<sw_grid, 256>>>(in2_W, seg2_W, meta_W, ctr_W, edge_W, ctr2_W,
                                     Whi, Wlo);

    // ---- init: input + seg branches ----
    lin1_kernel<<<lin_grid, 256>>>(nodes, 0, in1_W, in1_b, Ahi, Alo);
    gemm_tc_kernel<<<TC_GRID, TC_THREADS, TC_SMEM>>>(Ahi, Alo, sW(0), sL(0), H, NNODES);
    lin1_kernel<<<lin_grid, 256>>>(nodes, 2, seg1_W, seg1_b, Ahi, Alo);
    gemm_tc_kernel<<<TC_GRID, TC_THREADS, TC_SMEM>>>(Ahi, Alo, sW(1), sL(1), res, NNODES);
    gn2_kernel<<<gn_grid, 256>>>(H, in_g, in_bg, res, seg_g, seg_bg, feat, Ahi, Alo);

    // ---- meta: concat(feat, nodes[:,4:8]) @ meta_W.T -> GN -> relu ----
    gemm_tc_kernel<<<TC_GRID, TC_THREADS, TC_SMEM>>>(Ahi, Alo, sW(2), sL(2), tmp, NNODES);
    rank4_kernel<<<r4_grid, 256>>>(nodes, meta_W, tmp);
    gn_kernel<<<gn_grid, 256>>>(tmp, meta_g, meta_bg, nullptr, feat, res, Ahi, Alo, 1);

    // ---- 4 message-passing layers ----
    for (int i = 0; i < 4; i++) {
        gemm_tc_kernel<<<TC_GRID, TC_THREADS, TC_SMEM>>>(
            Ahi, Alo, sW(3 + i), sL(3 + i), tmp, NNODES);
        for (int t = 0; t < NTYPES; t++) {
            int s = 7 + i * NTYPES + t;
            gemm_tc_kernel<<<TC_GRID, TC_THREADS, TC_SMEM>>>(
                Ahi, Alo, sW(s), sL(s), H, NNODES);
            scatter_kernel<<<sc_grid, 256>>>(H, indexes, mask, t, tmp);
        }
        gn_kernel<<<gn_grid, 256>>>(tmp, norm_g + i * D, norm_bg + i * D,
                                    nullptr, feat, nullptr, Ahi, Alo, 1);
        gemm_tc_kernel<<<TC_GRID, TC_THREADS, TC_SMEM>>>(
            Ahi, Alo, sW(63 + i), sL(63 + i), tmp, NNODES);
        gn_kernel<<<gn_grid, 256>>>(tmp, ctr2_g + i * D, ctr2_bg + i * D,
                                    res, feat, res, Ahi, Alo, 1);   // feat = res
    }

    // ---- outputs ----
    int total = NNODES * D + NNODES * 2;
    copy_out_kernel<<<(total + 255) / 256, 256>>>(feat, nodes, out);
}

// round 8
// speedup vs baseline: 2.9137x; 1.0779x over previous
#include <cuda_runtime.h>
#include <cuda_bf16.h>
#include <math.h>
#include <stdint.h>

#define NNODES 100000
#define NEDGES 100000
#define D      128
#define NPAIRS 64
#define NTYPES 14
#define NSLOTS 67   // 0:in2 1:seg2 2:meta 3..6:ctr 7..62:edge 63..66:ctr2

#define SCAN_N   (NTYPES * NNODES)          // 1,400,000 (t,src) keys
#define SCAN_BLK 4096
#define SCAN_NBLK ((SCAN_N + SCAN_BLK - 1) / SCAN_BLK)   // 342

// ---------------- static device scratch ----------------
__device__ float    g_feat[NNODES * D];
__device__ float    g_res [NNODES * D];
__device__ float    g_tmp [NNODES * D];
__device__ float    g_H   [NNODES * D];
__device__ uint32_t g_Ahi [NNODES * NPAIRS];
__device__ uint32_t g_Alo [NNODES * NPAIRS];
__device__ uint32_t g_Whi [NSLOTS * D * NPAIRS];
__device__ uint32_t g_Wlo [NSLOTS * D * NPAIRS];
// CSR: edges grouped by (type, src)
__device__ int g_deg [SCAN_N];
__device__ int g_off [SCAN_N];
__device__ int g_cur [SCAN_N];
__device__ int g_dst [NTYPES * NEDGES];
__device__ int g_bsum[512];

// ---------------- helpers ----------------
__device__ __forceinline__ uint32_t pack_bf16x2(float e0, float e1) {
    uint32_t r;
    asm("cvt.rn.bf16x2.f32 %0, %1, %2;" : "=r"(r) : "f"(e1), "f"(e0));
    return r;
}
__device__ __forceinline__ void split_pair(float x0, float x1,
                                           uint32_t& hi, uint32_t& lo) {
    hi = pack_bf16x2(x0, x1);
    float h0 = __uint_as_float(hi << 16);
    float h1 = __uint_as_float(hi & 0xFFFF0000u);
    lo = pack_bf16x2(x0 - h0, x1 - h1);
}
__device__ __forceinline__ void mma_bf16(float* d, const uint32_t* a, const uint32_t* b) {
    asm volatile(
        "mma.sync.aligned.m16n8k16.row.col.f32.bf16.bf16.f32 "
        "{%0,%1,%2,%3}, {%4,%5,%6,%7}, {%8,%9}, {%0,%1,%2,%3};"
        : "+f"(d[0]), "+f"(d[1]), "+f"(d[2]), "+f"(d[3])
        : "r"(a[0]), "r"(a[1]), "r"(a[2]), "r"(a[3]), "r"(b[0]), "r"(b[1]));
}
__device__ __forceinline__ void red_v4(float* p, float4 v) {
    asm volatile("red.global.add.v4.f32 [%0], {%1, %2, %3, %4};"
                 :: "l"(p), "f"(v.x), "f"(v.y), "f"(v.z), "f"(v.w) : "memory");
}
__device__ __forceinline__ void cp16(void* dst_smem, const void* src) {
    uint32_t d = (uint32_t)__cvta_generic_to_shared(dst_smem);
    asm volatile("cp.async.ca.shared.global [%0], [%1], 16;" :: "r"(d), "l"(src));
}

// ---------------- CSR build ----------------
__global__ void zero_deg_kernel(int* deg) {
    int i = blockIdx.x * blockDim.x + threadIdx.x;
    if (i < SCAN_N) deg[i] = 0;
}
__global__ void deg_kernel(const int* __restrict__ indexes,
                           const int* __restrict__ mask, int* __restrict__ deg) {
    int idx = blockIdx.x * blockDim.x + threadIdx.x;
    if (idx >= NTYPES * NEDGES) return;
    int t = idx / NEDGES;
    int e = idx - t * NEDGES;
    if (e >= __ldg(mask + t)) return;
    int src = indexes[e * 28 + 2 * t + 1];
    atomicAdd(&deg[t * NNODES + src], 1);
}
// block-level exclusive scan: 256 thr x 16 elems
__global__ void scan1_kernel(const int* __restrict__ deg, int* __restrict__ off,
                             int* __restrict__ bsum) {
    __shared__ int warp_tot[8];
    int b = blockIdx.x, tid = threadIdx.x;
    int base = b * SCAN_BLK + tid * 16;
    int v[16];
    int run = 0;
    #pragma unroll
    for (int i = 0; i < 16; i++) {
        int idx = base + i;
        int t = (idx < SCAN_N) ? deg[idx] : 0;
        v[i] = run;
        run += t;
    }
    int lane = tid & 31, w = tid >> 5;
    int x = run;
    #pragma unroll
    for (int o = 1; o < 32; o <<= 1) {
        int y = __shfl_up_sync(0xffffffffu, x, o);
        if (lane >= o) x += y;
    }
    if (lane == 31) warp_tot[w] = x;
    __syncthreads();
    int woff = 0;
    for (int i = 0; i < w; i++) woff += warp_tot[i];
    int excl = x - run + woff;
    #pragma unroll
    for (int i = 0; i < 16; i++)
        if (base + i < SCAN_N) off[base + i] = v[i] + excl;
    if (tid == 255) bsum[b] = excl + run;
}
__global__ void scan2_kernel(int* bsum, int n) {   // 1 block, 512 thr
    __shared__ int sm[512];
    int tid = threadIdx.x;
    int v = (tid < n) ? bsum[tid] : 0;
    sm[tid] = v;
    __syncthreads();
    for (int o = 1; o < 512; o <<= 1) {
        int t = (tid >= o) ? sm[tid - o] : 0;
        __syncthreads();
        sm[tid] += t;
        __syncthreads();
    }
    if (tid < n) bsum[tid] = sm[tid] - v;   // exclusive
}
__global__ void scan3_kernel(int* __restrict__ off, const int* __restrict__ bsum,
                             int* __restrict__ cur) {
    int i = blockIdx.x * blockDim.x + threadIdx.x;
    if (i >= SCAN_N) return;
    int o = off[i] + bsum[i / SCAN_BLK];
    off[i] = o;
    cur[i] = o;
}
__global__ void fill_kernel(const int* __restrict__ indexes,
                            const int* __restrict__ mask,
                            int* __restrict__ cur, int* __restrict__ dstA) {
    int idx = blockIdx.x * blockDim.x + threadIdx.x;
    if (idx >= NTYPES * NEDGES) return;
    int t = idx / NEDGES;
    int e = idx - t * NEDGES;
    if (e >= __ldg(mask + t)) return;
    int src = indexes[e * 28 + 2 * t + 1];
    int dst = indexes[e * 28 + 2 * t];
    int pos = atomicAdd(&cur[t * NNODES + src], 1);
    dstA[pos] = dst;
}

// ---------------- pre-split weights ----------------
__global__ void split_w_kernel(const float* __restrict__ in2,
                               const float* __restrict__ seg2,
                               const float* __restrict__ meta,
                               const float* __restrict__ ctr,
                               const float* __restrict__ edge,
                               const float* __restrict__ ctr2,
                               uint32_t* __restrict__ Whi,
                               uint32_t* __restrict__ Wlo) {
    int idx = blockIdx.x * blockDim.x + threadIdx.x;
    if (idx >= NSLOTS * D * NPAIRS) return;
    int slot = idx / (D * NPAIRS);
    int r    = idx - slot * (D * NPAIRS);
    int c    = r >> 6;
    int p    = r & 63;
    int k0 = 2 * p;
    float x0, x1;
    if      (slot == 0) { x0 = in2 [c * D + k0]; x1 = in2 [c * D + k0 + 1]; }
    else if (slot == 1) { x0 = seg2[c * D + k0]; x1 = seg2[c * D + k0 + 1]; }
    else if (slot == 2) { x0 = meta[c * 132 + k0]; x1 = meta[c * 132 + k0 + 1]; }
    else if (slot < 7)  { const float* w = ctr  + (long)(slot - 3)  * D * D;
                          x0 = w[c * D + k0]; x1 = w[c * D + k0 + 1]; }
    else if (slot < 63) { const float* w = edge + (long)(slot - 7)  * D * D;
                          x0 = w[c * D + k0]; x1 = w[c * D + k0 + 1]; }
    else                { const float* w = ctr2 + (long)(slot - 63) * D * D;
                          x0 = w[c * D + k0]; x1 = w[c * D + k0 + 1]; }
    uint32_t hi, lo;
    split_pair(x0, x1, hi, lo);
    Whi[idx] = hi;
    Wlo[idx] = lo;
}

// ---------------- lin1 ----------------
__global__ void lin1_kernel(const float* __restrict__ nodes, int off,
                            const float* __restrict__ W1, const float* __restrict__ b1,
                            uint32_t* __restrict__ Ahi, uint32_t* __restrict__ Alo) {
    int idx = blockIdx.x * blockDim.x + threadIdx.x;
    if (idx >= NNODES * NPAIRS) return;
    int n = idx >> 6;
    int p = idx & 63;
    int j0 = 2 * p;
    float x0 = nodes[n * 8 + off];
    float x1 = nodes[n * 8 + off + 1];
    float v0 = fmaxf(fmaf(x0, W1[j0 * 2],     fmaf(x1, W1[j0 * 2 + 1], b1[j0])),     0.0f);
    float v1 = fmaxf(fmaf(x0, W1[j0 * 2 + 2], fmaf(x1, W1[j0 * 2 + 3], b1[j0 + 1])), 0.0f);
    uint32_t hi, lo;
    split_pair(v0, v1, hi, lo);
    Ahi[idx] = hi;
    Alo[idx] = lo;
}

// ---------------- plain GEMM (init/meta/ctr2): round-5 proven kernel --------------
#define TC_THREADS 256
#define SW_STR     68
#define TC_SMEM    (2 * D * SW_STR * 4)
#define TC_GRID    296

__global__ void __launch_bounds__(TC_THREADS, 2)
gemm_tc_kernel(const uint32_t* __restrict__ Ahi, const uint32_t* __restrict__ Alo,
               const uint32_t* __restrict__ Whi, const uint32_t* __restrict__ Wlo,
               float* __restrict__ C, int nrows) {
    extern __shared__ uint32_t sm[];
    uint32_t* sWhi = sm;
    uint32_t* sWlo = sm + D * SW_STR;
    int tid = threadIdx.x;

    for (int idx = tid; idx < D * NPAIRS; idx += TC_THREADS) {
        int c = idx >> 6;
        int p = idx & 63;
        sWhi[c * SW_STR + p] = Whi[idx];
        sWlo[c * SW_STR + p] = Wlo[idx];
    }
    __syncthreads();

    int wid  = tid >> 5;
    int lane = tid & 31;
    int rgrp = wid >> 1;
    int cgrp = wid & 1;
    int qr = lane >> 2;
    int qk = lane & 3;

    int ntiles = (nrows + 127) / 128;
    for (int tile = blockIdx.x; tile < ntiles; tile += gridDim.x) {
        int rbase = tile * 128 + rgrp * 32;
        int r00 = rbase + qr;
        int r01 = rbase + qr + 8;
        int r10 = rbase + 16 + qr;
        int r11 = rbase + 16 + qr + 8;
        bool v00 = r00 < nrows, v01 = r01 < nrows;
        bool v10 = r10 < nrows, v11 = r11 < nrows;

        float acc[2][8][4];
        #pragma unroll
        for (int s = 0; s < 2; s++)
            #pragma unroll
            for (int nt = 0; nt < 8; nt++)
                #pragma unroll
                for (int j = 0; j < 4; j++) acc[s][nt][j] = 0.0f;

        #pragma unroll
        for (int kt = 0; kt < 8; kt++) {
            int p0 = kt * 8 + qk;
            int p1 = p0 + 4;
            uint32_t ah0[4], al0[4], ah1[4], al1[4];
            ah0[0] = v00 ? Ahi[(long)r00 * NPAIRS + p0] : 0u;
            ah0[1] = v01 ? Ahi[(long)r01 * NPAIRS + p0] : 0u;
            ah0[2] = v00 ? Ahi[(long)r00 * NPAIRS + p1] : 0u;
            ah0[3] = v01 ? Ahi[(long)r01 * NPAIRS + p1] : 0u;
            al0[0] = v00 ? Alo[(long)r00 * NPAIRS + p0] : 0u;
            al0[1] = v01 ? Alo[(long)r01 * NPAIRS + p0] : 0u;
            al0[2] = v00 ? Alo[(long)r00 * NPAIRS + p1] : 0u;
            al0[3] = v01 ? Alo[(long)r01 * NPAIRS + p1] : 0u;
            ah1[0] = v10 ? Ahi[(long)r10 * NPAIRS + p0] : 0u;
            ah1[1] = v11 ? Ahi[(long)r11 * NPAIRS + p0] : 0u;
            ah1[2] = v10 ? Ahi[(long)r10 * NPAIRS + p1] : 0u;
            ah1[3] = v11 ? Ahi[(long)r11 * NPAIRS + p1] : 0u;
            al1[0] = v10 ? Alo[(long)r10 * NPAIRS + p0] : 0u;
            al1[1] = v11 ? Alo[(long)r11 * NPAIRS + p0] : 0u;
            al1[2] = v10 ? Alo[(long)r10 * NPAIRS + p1] : 0u;
            al1[3] = v11 ? Alo[(long)r11 * NPAIRS + p1] : 0u;

            #pragma unroll
            for (int nt = 0; nt < 8; nt++) {
                int n = cgrp * 64 + nt * 8 + qr;
                int off = n * SW_STR;
                uint32_t bh[2], bl[2];
                bh[0] = sWhi[off + p0];
                bh[1] = sWhi[off + p1];
                bl[0] = sWlo[off + p0];
                bl[1] = sWlo[off + p1];
                mma_bf16(acc[0][nt], ah0, bh);
                mma_bf16(acc[0][nt], al0, bh);
                mma_bf16(acc[0][nt], ah0, bl);
                mma_bf16(acc[1][nt], ah1, bh);
                mma_bf16(acc[1][nt], al1, bh);
                mma_bf16(acc[1][nt], ah1, bl);
            }
        }

        #pragma unroll
        for (int nt = 0; nt < 8; nt++) {
            int col = cgrp * 64 + nt * 8 + 2 * qk;
            if (v00) *reinterpret_cast<float2*>(C + (long)r00 * D + col) =
                         make_float2(acc[0][nt][0], acc[0][nt][1]);
            if (v01) *reinterpret_cast<float2*>(C + (long)r01 * D + col) =
                         make_float2(acc[0][nt][2], acc[0][nt][3]);
            if (v10) *reinterpret_cast<float2*>(C + (long)r10 * D + col) =
                         make_float2(acc[1][nt][0], acc[1][nt][1]);
            if (v11) *reinterpret_cast<float2*>(C + (long)r11 * D + col) =
                         make_float2(acc[1][nt][2], acc[1][nt][3]);
        }
    }
}

// ---------------- fused message-passing layer kernel ----------------
// One block = 128 rows, 8 warps x 16 rows x 128 cols. A fragments in registers.
// Loops 15 slots: s=0 ctr (self-edge red), s=1..14 edge types (CSR red scatter).
// W double-buffered in smem via cp.async. Warp-private smem staging for scatter.
#define MP_THREADS 256
#define MP_GRID    ((NNODES + 127) / 128)
#define MP_WBUF    (D * SW_STR)                       // words per (hi or lo) buffer
#define MP_STG_STR 132
#define MP_SMEM    ((4 * MP_WBUF + 8 * 16 * MP_STG_STR) * 4)

__global__ void __launch_bounds__(MP_THREADS, 1)
mp_kernel(const uint32_t* __restrict__ Ahi, const uint32_t* __restrict__ Alo,
          const uint32_t* __restrict__ Whi, const uint32_t* __restrict__ Wlo,
          int layer,
          const int* __restrict__ off, const int* __restrict__ deg,
          const int* __restrict__ dstA,
          float* __restrict__ tmp, int nrows) {
    extern __shared__ uint32_t smp[];
    uint32_t* bufhi[2] = { smp,              smp + 2 * MP_WBUF };
    uint32_t* buflo[2] = { smp + MP_WBUF,    smp + 3 * MP_WBUF };
    float* stage = reinterpret_cast<float*>(smp + 4 * MP_WBUF);

    int tid  = threadIdx.x;
    int wid  = tid >> 5;
    int lane = tid & 31;
    int qr = lane >> 2;
    int qk = lane & 3;

    int rbase = blockIdx.x * 128 + wid * 16;
    int r0 = rbase + qr;
    int r1 = rbase + qr + 8;
    bool v0 = r0 < nrows;
    bool v1 = r1 < nrows;

    // ---- load A fragments for all kt (once per block) ----
    uint32_t ah[8][4], al[8][4];
    #pragma unroll
    for (int kt = 0; kt < 8; kt++) {
        int p0 = kt * 8 + qk;
        int p1 = p0 + 4;
        ah[kt][0] = v0 ? Ahi[(long)r0 * NPAIRS + p0] : 0u;
        ah[kt][1] = v1 ? Ahi[(long)r1 * NPAIRS + p0] : 0u;
        ah[kt][2] = v0 ? Ahi[(long)r0 * NPAIRS + p1] : 0u;
        ah[kt][3] = v1 ? Ahi[(long)r1 * NPAIRS + p1] : 0u;
        al[kt][0] = v0 ? Alo[(long)r0 * NPAIRS + p0] : 0u;
        al[kt][1] = v1 ? Alo[(long)r1 * NPAIRS + p0] : 0u;
        al[kt][2] = v0 ? Alo[(long)r0 * NPAIRS + p1] : 0u;
        al[kt][3] = v1 ? Alo[(long)r1 * NPAIRS + p1] : 0u;
    }

    // slot index helper: s=0 -> ctr(3+layer); s>=1 -> 7 + layer*14 + (s-1)
    auto slot_of = [&](int s) { return (s == 0) ? (3 + layer) : (7 + layer * NTYPES + s - 1); };

    // preload slot 0 into buffer 0
    {
        const uint32_t* wh = Whi + (long)slot_of(0) * D * NPAIRS;
        const uint32_t* wl = Wlo + (long)slot_of(0) * D * NPAIRS;
        for (int i4 = tid * 4; i4 < D * NPAIRS; i4 += MP_THREADS * 4) {
            int c = i4 >> 6, p = i4 & 63;
            cp16(&bufhi[0][c * SW_STR + p], wh + i4);
            cp16(&buflo[0][c * SW_STR + p], wl + i4);
        }
        asm volatile("cp.async.commit_group;");
        asm volatile("cp.async.wait_group 0;");
    }
    __syncthreads();

    int cur = 0;
    for (int s = 0; s < 15; s++) {
        // prefetch next slot into the other buffer
        if (s + 1 < 15) {
            const uint32_t* wh = Whi + (long)slot_of(s + 1) * D * NPAIRS;
            const uint32_t* wl = Wlo + (long)slot_of(s + 1) * D * NPAIRS;
            int nb = cur ^ 1;
            for (int i4 = tid * 4; i4 < D * NPAIRS; i4 += MP_THREADS * 4) {
                int c = i4 >> 6, p = i4 & 63;
                cp16(&bufhi[nb][c * SW_STR + p], wh + i4);
                cp16(&buflo[nb][c * SW_STR + p], wl + i4);
            }
        }
        asm volatile("cp.async.commit_group;");

        // ---- MMA: 16 rows x 128 cols from A regs x W smem ----
        const uint32_t* sWhi = bufhi[cur];
        const uint32_t* sWlo = buflo[cur];
        float acc[16][4];
        #pragma unroll
        for (int nt = 0; nt < 16; nt++)
            #pragma unroll
            for (int j = 0; j < 4; j++) acc[nt][j] = 0.0f;

        #pragma unroll
        for (int kt = 0; kt < 8; kt++) {
            int p0 = kt * 8 + qk;
            int p1 = p0 + 4;
            #pragma unroll
            for (int nt = 0; nt < 16; nt++) {
                int woff = (nt * 8 + qr) * SW_STR;
                uint32_t bh[2], bl[2];
                bh[0] = sWhi[woff + p0];
                bh[1] = sWhi[woff + p1];
                bl[0] = sWlo[woff + p0];
                bl[1] = sWlo[woff + p1];
                mma_bf16(acc[nt], ah[kt], bh);
                mma_bf16(acc[nt], al[kt], bh);
                mma_bf16(acc[nt], ah[kt], bl);
            }
        }

        // ---- stage warp tile to warp-private smem ----
        float* st = stage + wid * (16 * MP_STG_STR);
        #pragma unroll
        for (int nt = 0; nt < 16; nt++) {
            int c = nt * 8 + 2 * qk;
            *reinterpret_cast<float2*>(&st[qr * MP_STG_STR + c]) =
                make_float2(acc[nt][0], acc[nt][1]);
            *reinterpret_cast<float2*>(&st[(qr + 8) * MP_STG_STR + c]) =
                make_float2(acc[nt][2], acc[nt][3]);
        }
        __syncwarp();

        // ---- scatter epilogue ----
        if (s == 0) {
            for (int rr = 0; rr < 16; rr++) {
                int row = rbase + rr;
                if (row >= nrows) break;
                float4 v = *reinterpret_cast<float4*>(&st[rr * MP_STG_STR + lane * 4]);
                red_v4(tmp + (long)row * D + lane * 4, v);
            }
        } else {
            int t = s - 1;
            for (int rr = 0; rr < 16; rr++) {
                int row = rbase + rr;
                if (row >= nrows) break;
                long key = (long)t * NNODES + row;
                int o0 = __ldg(off + key);
                int dg = __ldg(deg + key);
                if (dg == 0) continue;
                float4 v = *reinterpret_cast<float4*>(&st[rr * MP_STG_STR + lane * 4]);
                for (int j = 0; j < dg; j++) {
                    int d = __ldg(dstA + o0 + j);
                    red_v4(tmp + (long)d * D + lane * 4, v);
                }
            }
        }
        __syncwarp();

        __syncthreads();                        // all reads of buf[cur] done
        asm volatile("cp.async.wait_group 0;"); // next W landed
        __syncthreads();
        cur ^= 1;
    }
}

// ---------------- GroupNorm helpers ----------------
__device__ __forceinline__ float warp_sum(float v) {
    #pragma unroll
    for (int o = 16; o > 0; o >>= 1) v += __shfl_xor_sync(0xffffffffu, v, o);
    return v;
}
__device__ __forceinline__ void store_split4(uint32_t* Ahi, uint32_t* Alo,
                                             int row, int lane, float4 y) {
    uint32_t h0, l0, h1, l1;
    split_pair(y.x, y.y, h0, l0);
    split_pair(y.z, y.w, h1, l1);
    *reinterpret_cast<uint2*>(Ahi + (long)row * NPAIRS + lane * 2) = make_uint2(h0, h1);
    *reinterpret_cast<uint2*>(Alo + (long)row * NPAIRS + lane * 2) = make_uint2(l0, l1);
}

// out1 = maybe_relu(gn(in)*g+b [+resid]); optional dup out2; split out; optional zero-fill zbuf
__global__ void gn_kernel(const float* __restrict__ in,
                          const float* __restrict__ g, const float* __restrict__ b,
                          const float* __restrict__ resid,
                          float* __restrict__ out1, float* __restrict__ out2,
                          uint32_t* __restrict__ Ahi, uint32_t* __restrict__ Alo,
                          float* __restrict__ zbuf,
                          int do_relu) {
    int warp = (blockIdx.x * blockDim.x + threadIdx.x) >> 5;
    int lane = threadIdx.x & 31;
    if (warp >= NNODES) return;
    const float4 x = *reinterpret_cast<const float4*>(in + (long)warp * D + lane * 4);
    float s  = x.x + x.y + x.z + x.w;
    float ss = x.x * x.x + x.y * x.y + x.z * x.z + x.w * x.w;
    s  = warp_sum(s);
    ss = warp_sum(ss);
    float m   = s * (1.0f / 128.0f);
    float var = ss * (1.0f / 128.0f) - m * m;
    float inv = rsqrtf(var + 1e-5f);
    float4 gg = *reinterpret_cast<const float4*>(g + lane * 4);
    float4 bb = *reinterpret_cast<const float4*>(b + lane * 4);
    float4 y;
    y.x = fmaf((x.x - m) * inv, gg.x, bb.x);
    y.y = fmaf((x.y - m) * inv, gg.y, bb.y);
    y.z = fmaf((x.z - m) * inv, gg.z, bb.z);
    y.w = fmaf((x.w - m) * inv, gg.w, bb.w);
    if (resid) {
        float4 r = *reinterpret_cast<const float4*>(resid + (long)warp * D + lane * 4);
        y.x += r.x; y.y += r.y; y.z += r.z; y.w += r.w;
    }
    if (do_relu) {
        y.x = fmaxf(y.x, 0.0f); y.y = fmaxf(y.y, 0.0f);
        y.z = fmaxf(y.z, 0.0f); y.w = fmaxf(y.w, 0.0f);
    }
    *reinterpret_cast<float4*>(out1 + (long)warp * D + lane * 4) = y;
    if (out2)
        *reinterpret_cast<float4*>(out2 + (long)warp * D + lane * 4) = y;
    if (Ahi) store_split4(Ahi, Alo, warp, lane, y);
    if (zbuf)
        *reinterpret_cast<float4*>(zbuf + (long)warp * D + lane * 4) =
            make_float4(0.f, 0.f, 0.f, 0.f);
}

// out = relu( gn(inA)*gA+bA + gn(inB)*gB+bB ), plus split output
__global__ void gn2_kernel(const float* __restrict__ inA,
                           const float* __restrict__ gA, const float* __restrict__ bA,
                           const float* __restrict__ inB,
                           const float* __restrict__ gB, const float* __restrict__ bB,
                           float* __restrict__ out,
                           uint32_t* __restrict__ Ahi, uint32_t* __restrict__ Alo) {
    int warp = (blockIdx.x * blockDim.x + threadIdx.x) >> 5;
    int lane = threadIdx.x & 31;
    if (warp >= NNODES) return;
    const float4 xa = *reinterpret_cast<const float4*>(inA + (long)warp * D + lane * 4);
    const float4 xb = *reinterpret_cast<const float4*>(inB + (long)warp * D + lane * 4);
    float sa  = xa.x + xa.y + xa.z + xa.w;
    float ssa = xa.x * xa.x + xa.y * xa.y + xa.z * xa.z + xa.w * xa.w;
    float sb  = xb.x + xb.y + xb.z + xb.w;
    float ssb = xb.x * xb.x + xb.y * xb.y + xb.z * xb.z + xb.w * xb.w;
    sa = warp_sum(sa); ssa = warp_sum(ssa);
    sb = warp_sum(sb); ssb = warp_sum(ssb);
    float ma = sa * (1.0f / 128.0f);
    float mb = sb * (1.0f / 128.0f);
    float ia = rsqrtf(ssa * (1.0f / 128.0f) - ma * ma + 1e-5f);
    float ib = rsqrtf(ssb * (1.0f / 128.0f) - mb * mb + 1e-5f);
    float4 ga4 = *reinterpret_cast<const float4*>(gA + lane * 4);
    float4 ba4 = *reinterpret_cast<const float4*>(bA + lane * 4);
    float4 gb4 = *reinterpret_cast<const float4*>(gB + lane * 4);
    float4 bb4 = *reinterpret_cast<const float4*>(bB + lane * 4);
    float4 y;
    y.x = fmaf((xa.x - ma) * ia, ga4.x, ba4.x) + fmaf((xb.x - mb) * ib, gb4.x, bb4.x);
    y.y = fmaf((xa.y - ma) * ia, ga4.y, ba4.y) + fmaf((xb.y - mb) * ib, gb4.y, bb4.y);
    y.z = fmaf((xa.z - ma) * ia, ga4.z, ba4.z) + fmaf((xb.z - mb) * ib, gb4.z, bb4.z);
    y.w = fmaf((xa.w - ma) * ia, ga4.w, ba4.w) + fmaf((xb.w - mb) * ib, gb4.w, bb4.w);
    y.x = fmaxf(y.x, 0.0f); y.y = fmaxf(y.y, 0.0f);
    y.z = fmaxf(y.z, 0.0f); y.w = fmaxf(y.w, 0.0f);
    *reinterpret_cast<float4*>(out + (long)warp * D + lane * 4) = y;
    store_split4(Ahi, Alo, warp, lane, y);
}

// ---------------- rank-4 update ----------------
__global__ void rank4_kernel(const float* __restrict__ nodes,
                             const float* __restrict__ metaW,
                             float* __restrict__ out) {
    int idx = blockIdx.x * blockDim.x + threadIdx.x;
    if (idx >= NNODES * D) return;
    int n = idx >> 7;
    int c = idx & 127;
    const float* wr = metaW + c * 132 + 128;
    const float* nd = nodes + n * 8 + 4;
    float s = fmaf(nd[0], wr[0], fmaf(nd[1], wr[1], fmaf(nd[2], wr[2], nd[3] * wr[3])));
    out[idx] += s;
}

// ---------------- final output ----------------
__global__ void copy_out_kernel(const float* __restrict__ feat,
                                const float* __restrict__ nodes,
                                float* __restrict__ out) {
    int idx = blockIdx.x * blockDim.x + threadIdx.x;
    const int F = NNODES * D;
    if (idx < F) {
        out[idx] = feat[idx];
    } else if (idx < F + NNODES * 2) {
        int j = idx - F;
        int n = j >> 1;
        int c = j & 1;
        out[idx] = nodes[n * 8 + c];
    }
}

// ---------------- host launcher ----------------
extern "C" void kernel_launch(void* const* d_in, const int* in_sizes, int n_in,
                              void* d_out, int out_size) {
    const float* nodes   = (const float*)d_in[0];
    const int*   indexes = (const int*)  d_in[1];
    const int*   mask    = (const int*)  d_in[2];
    const float* in1_W   = (const float*)d_in[3];
    const float* in1_b   = (const float*)d_in[4];
    const float* in2_W   = (const float*)d_in[5];
    const float* in_g    = (const float*)d_in[6];
    const float* in_bg   = (const float*)d_in[7];
    const float* seg1_W  = (const float*)d_in[8];
    const float* seg1_b  = (const float*)d_in[9];
    const float* seg2_W  = (const float*)d_in[10];
    const float* seg_g   = (const float*)d_in[11];
    const float* seg_bg  = (const float*)d_in[12];
    const float* meta_W  = (const float*)d_in[13];
    const float* meta_g  = (const float*)d_in[14];
    const float* meta_bg = (const float*)d_in[15];
    const float* ctr_W   = (const float*)d_in[16];
    const float* edge_W  = (const float*)d_in[17];
    const float* norm_g  = (const float*)d_in[18];
    const float* norm_bg = (const float*)d_in[19];
    const float* ctr2_W  = (const float*)d_in[20];
    const float* ctr2_g  = (const float*)d_in[21];
    const float* ctr2_bg = (const float*)d_in[22];
    float* out = (float*)d_out;

    float *feat, *res, *tmp, *H;
    uint32_t *Whi, *Wlo, *Ahi, *Alo;
    int *deg, *off, *cur, *dstA, *bsum;
    cudaGetSymbolAddress((void**)&feat, g_feat);
    cudaGetSymbolAddress((void**)&res,  g_res);
    cudaGetSymbolAddress((void**)&tmp,  g_tmp);
    cudaGetSymbolAddress((void**)&H,    g_H);
    cudaGetSymbolAddress((void**)&Whi,  g_Whi);
    cudaGetSymbolAddress((void**)&Wlo,  g_Wlo);
    cudaGetSymbolAddress((void**)&Ahi,  g_Ahi);
    cudaGetSymbolAddress((void**)&Alo,  g_Alo);
    cudaGetSymbolAddress((void**)&deg,  g_deg);
    cudaGetSymbolAddress((void**)&off,  g_off);
    cudaGetSymbolAddress((void**)&cur,  g_cur);
    cudaGetSymbolAddress((void**)&dstA, g_dst);
    cudaGetSymbolAddress((void**)&bsum, g_bsum);

    cudaFuncSetAttribute(gemm_tc_kernel,
                         cudaFuncAttributeMaxDynamicSharedMemorySize, TC_SMEM);
    cudaFuncSetAttribute(mp_kernel,
                         cudaFuncAttributeMaxDynamicSharedMemorySize, MP_SMEM);

    const int lin_grid = (NNODES * NPAIRS + 255) / 256;
    const int gn_grid  = (NNODES * 32 + 255) / 256;
    const int sw_grid  = (NSLOTS * D * NPAIRS + 255) / 256;
    const int r4_grid  = (NNODES * D + 255) / 256;
    const int te_grid  = (NTYPES * NEDGES + 255) / 256;
    const int zn_grid  = (SCAN_N + 255) / 256;

    auto sWp = [&](int s) { return Whi + (long)s * D * NPAIRS; };
    auto sLp = [&](int s) { return Wlo + (long)s * D * NPAIRS; };

    // ---- CSR build (edges grouped by (type, src)) ----
    zero_deg_kernel<<<zn_grid, 256>>>(deg);
    deg_kernel<<<te_grid, 256>>>(indexes, mask, deg);
    scan1_kernel<<<SCAN_NBLK, 256>>>(deg, off, bsum);
    scan2_kernel<<<1, 512>>>(bsum, SCAN_NBLK);
    scan3_kernel<<<zn_grid, 256>>>(off, bsum, cur);
    fill_kernel<<<te_grid, 256>>>(indexes, mask, cur, dstA);

    // ---- pre-split weights ----
    split_w_kernel<<<sw_grid, 256>>>(in2_W, seg2_W, meta_W, ctr_W, edge_W, ctr2_W,
                                     Whi, Wlo);

    // ---- init: input + seg branches ----
    lin1_kernel<<<lin_grid, 256>>>(nodes, 0, in1_W, in1_b, Ahi, Alo);
    gemm_tc_kernel<<<TC_GRID, TC_THREADS, TC_SMEM>>>(Ahi, Alo, sWp(0), sLp(0), H, NNODES);
    lin1_kernel<<<lin_grid, 256>>>(nodes, 2, seg1_W, seg1_b, Ahi, Alo);
    gemm_tc_kernel<<<TC_GRID, TC_THREADS, TC_SMEM>>>(Ahi, Alo, sWp(1), sLp(1), res, NNODES);
    gn2_kernel<<<gn_grid, 256>>>(H, in_g, in_bg, res, seg_g, seg_bg, feat, Ahi, Alo);

    // ---- meta ----
    gemm_tc_kernel<<<TC_GRID, TC_THREADS, TC_SMEM>>>(Ahi, Alo, sWp(2), sLp(2), tmp, NNODES);
    rank4_kernel<<<r4_grid, 256>>>(nodes, meta_W, tmp);
    // feat = relu(gn(tmp)); res = feat; split; zero tmp for layer-0 mp
    gn_kernel<<<gn_grid, 256>>>(tmp, meta_g, meta_bg, nullptr, feat, res, Ahi, Alo, tmp, 1);

    // ---- 4 message-passing layers ----
    for (int i = 0; i < 4; i++) {
        // tmp += feat@ctrW + sum_t scatter(feat@edgeW_t)   (tmp pre-zeroed)
        mp_kernel<<<MP_GRID, MP_THREADS, MP_SMEM>>>(Ahi, Alo, Whi, Wlo, i,
                                                    off, deg, dstA, tmp, NNODES);
        // feat = relu(gn(tmp)); split
        gn_kernel<<<gn_grid, 256>>>(tmp, norm_g + i * D, norm_bg + i * D,
                                    nullptr, feat, nullptr, Ahi, Alo, nullptr, 1);
        // tmp = feat @ ctr2W
        gemm_tc_kernel<<<TC_GRID, TC_THREADS, TC_SMEM>>>(
            Ahi, Alo, sWp(63 + i), sLp(63 + i), tmp, NNODES);
        // feat = res = relu(gn(tmp) + res); split; zero tmp for next layer
        gn_kernel<<<gn_grid, 256>>>(tmp, ctr2_g + i * D, ctr2_bg + i * D,
                                    res, feat, res, Ahi, Alo,
                                    (i < 3) ? tmp : nullptr, 1);
    }

    // ---- outputs ----
    int total = NNODES * D + NNODES * 2;
    copy_out_kernel<<<(total + 255) / 256, 256>>>(feat, nodes, out);
}

// round 10
// speedup vs baseline: 3.0826x; 1.0580x over previous
#include <cuda_runtime.h>
#include <cuda_bf16.h>
#include <math.h>
#include <stdint.h>

#define NNODES 100000
#define NEDGES 100000
#define D      128
#define NPAIRS 64
#define NTYPES 14
#define NSLOTS 67   // 0:in2 1:seg2 2:meta 3..6:ctr 7..62:edge 63..66:ctr2

#define SCAN_N   (NTYPES * NNODES)
#define SCAN_BLK 4096
#define SCAN_NBLK ((SCAN_N + SCAN_BLK - 1) / SCAN_BLK)

// ---------------- static device scratch ----------------
__device__ float    g_feat[NNODES * D];
__device__ float    g_res [NNODES * D];
__device__ float    g_tmp [NNODES * D];
__device__ uint32_t g_Ahi [NNODES * NPAIRS];
__device__ uint32_t g_Alo [NNODES * NPAIRS];
__device__ uint32_t g_Whi [NSLOTS * D * NPAIRS];   // pair-interleaved layout
__device__ uint32_t g_Wlo [NSLOTS * D * NPAIRS];
__device__ float    g_H  [NNODES * D];
__device__ int g_deg [SCAN_N];
__device__ int g_off [SCAN_N];
__device__ int g_cur [SCAN_N];
__device__ int g_dst [NTYPES * NEDGES];
__device__ int g_bsum[512];

// ---------------- generic helpers ----------------
__device__ __forceinline__ uint32_t pack_bf16x2(float e0, float e1) {
    uint32_t r;
    asm("cvt.rn.bf16x2.f32 %0, %1, %2;" : "=r"(r) : "f"(e1), "f"(e0));
    return r;
}
__device__ __forceinline__ void split_pair(float x0, float x1,
                                           uint32_t& hi, uint32_t& lo) {
    hi = pack_bf16x2(x0, x1);
    float h0 = __uint_as_float(hi << 16);
    float h1 = __uint_as_float(hi & 0xFFFF0000u);
    lo = pack_bf16x2(x0 - h0, x1 - h1);
}
__device__ __forceinline__ void mma_bf16(float* d, const uint32_t* a, const uint32_t* b) {
    asm volatile(
        "mma.sync.aligned.m16n8k16.row.col.f32.bf16.bf16.f32 "
        "{%0,%1,%2,%3}, {%4,%5,%6,%7}, {%8,%9}, {%0,%1,%2,%3};"
        : "+f"(d[0]), "+f"(d[1]), "+f"(d[2]), "+f"(d[3])
        : "r"(a[0]), "r"(a[1]), "r"(a[2]), "r"(a[3]), "r"(b[0]), "r"(b[1]));
}
__device__ __forceinline__ void red_v4(float* p, float4 v) {
    asm volatile("red.global.add.v4.f32 [%0], {%1, %2, %3, %4};"
                 :: "l"(p), "f"(v.x), "f"(v.y), "f"(v.z), "f"(v.w) : "memory");
}
__device__ __forceinline__ void cp16(uint32_t dst_smem, const void* src) {
    asm volatile("cp.async.ca.shared.global [%0], [%1], 16;" :: "r"(dst_smem), "l"(src));
}
__device__ __forceinline__ uint32_t smem_u32(const void* p) {
    uint32_t a;
    asm("{ .reg .u64 t; cvta.to.shared.u64 t, %1; cvt.u32.u64 %0, t; }" : "=r"(a) : "l"(p));
    return a;
}

// ---------------- CSR build ----------------
__global__ void zero_deg_kernel(int* deg) {
    int i = blockIdx.x * blockDim.x + threadIdx.x;
    if (i < SCAN_N) deg[i] = 0;
}
__global__ void deg_kernel(const int* __restrict__ indexes,
                           const int* __restrict__ mask, int* __restrict__ deg) {
    int idx = blockIdx.x * blockDim.x + threadIdx.x;
    if (idx >= NTYPES * NEDGES) return;
    int t = idx / NEDGES;
    int e = idx - t * NEDGES;
    if (e >= __ldg(mask + t)) return;
    int src = indexes[e * 28 + 2 * t + 1];
    atomicAdd(&deg[t * NNODES + src], 1);
}
__global__ void scan1_kernel(const int* __restrict__ deg, int* __restrict__ off,
                             int* __restrict__ bsum) {
    __shared__ int warp_tot[8];
    int b = blockIdx.x, tid = threadIdx.x;
    int base = b * SCAN_BLK + tid * 16;
    int v[16];
    int run = 0;
    #pragma unroll
    for (int i = 0; i < 16; i++) {
        int idx = base + i;
        int t = (idx < SCAN_N) ? deg[idx] : 0;
        v[i] = run;
        run += t;
    }
    int lane = tid & 31, w = tid >> 5;
    int x = run;
    #pragma unroll
    for (int o = 1; o < 32; o <<= 1) {
        int y = __shfl_up_sync(0xffffffffu, x, o);
        if (lane >= o) x += y;
    }
    if (lane == 31) warp_tot[w] = x;
    __syncthreads();
    int woff = 0;
    for (int i = 0; i < w; i++) woff += warp_tot[i];
    int excl = x - run + woff;
    #pragma unroll
    for (int i = 0; i < 16; i++)
        if (base + i < SCAN_N) off[base + i] = v[i] + excl;
    if (tid == 255) bsum[b] = excl + run;
}
__global__ void scan2_kernel(int* bsum, int n) {
    __shared__ int sm[512];
    int tid = threadIdx.x;
    int v = (tid < n) ? bsum[tid] : 0;
    sm[tid] = v;
    __syncthreads();
    for (int o = 1; o < 512; o <<= 1) {
        int t = (tid >= o) ? sm[tid - o] : 0;
        __syncthreads();
        sm[tid] += t;
        __syncthreads();
    }
    if (tid < n) bsum[tid] = sm[tid] - v;
}
__global__ void scan3_kernel(int* __restrict__ off, const int* __restrict__ bsum,
                             int* __restrict__ cur) {
    int i = blockIdx.x * blockDim.x + threadIdx.x;
    if (i >= SCAN_N) return;
    int o = off[i] + bsum[i / SCAN_BLK];
    off[i] = o;
    cur[i] = o;
}
__global__ void fill_kernel(const int* __restrict__ indexes,
                            const int* __restrict__ mask,
                            int* __restrict__ cur, int* __restrict__ dstA) {
    int idx = blockIdx.x * blockDim.x + threadIdx.x;
    if (idx >= NTYPES * NEDGES) return;
    int t = idx / NEDGES;
    int e = idx - t * NEDGES;
    if (e >= __ldg(mask + t)) return;
    int src = indexes[e * 28 + 2 * t + 1];
    int dst = indexes[e * 28 + 2 * t];
    int pos = atomicAdd(&cur[t * NNODES + src], 1);
    dstA[pos] = dst;
}

// ---------------- pre-split weights (PAIR-INTERLEAVED gmem layout) -------------
// output index c*64 + ip, where ip = kt*8 + 2*qk + j  <->  original pair p = kt*8 + qk + 4*j
__global__ void split_w_kernel(const float* __restrict__ in2,
                               const float* __restrict__ seg2,
                               const float* __restrict__ meta,
                               const float* __restrict__ ctr,
                               const float* __restrict__ edge,
                               const float* __restrict__ ctr2,
                               uint32_t* __restrict__ Whi,
                               uint32_t* __restrict__ Wlo) {
    int idx = blockIdx.x * blockDim.x + threadIdx.x;
    if (idx >= NSLOTS * D * NPAIRS) return;
    int slot = idx / (D * NPAIRS);
    int r    = idx - slot * (D * NPAIRS);
    int c    = r >> 6;
    int ip   = r & 63;
    int g  = ip >> 3;
    int w  = ip & 7;
    int qk = w >> 1;
    int j  = w & 1;
    int p  = 8 * g + qk + 4 * j;
    int k0 = 2 * p;
    float x0, x1;
    if      (slot == 0) { x0 = in2 [c * D + k0]; x1 = in2 [c * D + k0 + 1]; }
    else if (slot == 1) { x0 = seg2[c * D + k0]; x1 = seg2[c * D + k0 + 1]; }
    else if (slot == 2) { x0 = meta[c * 132 + k0]; x1 = meta[c * 132 + k0 + 1]; }
    else if (slot < 7)  { const float* wm = ctr  + (long)(slot - 3)  * D * D;
                          x0 = wm[c * D + k0]; x1 = wm[c * D + k0 + 1]; }
    else if (slot < 63) { const float* wm = edge + (long)(slot - 7)  * D * D;
                          x0 = wm[c * D + k0]; x1 = wm[c * D + k0 + 1]; }
    else                { const float* wm = ctr2 + (long)(slot - 63) * D * D;
                          x0 = wm[c * D + k0]; x1 = wm[c * D + k0 + 1]; }
    uint32_t hi, lo;
    split_pair(x0, x1, hi, lo);
    Whi[idx] = hi;
    Wlo[idx] = lo;
}

// ---------------- lin1 ----------------
__global__ void lin1_kernel(const float* __restrict__ nodes, int off,
                            const float* __restrict__ W1, const float* __restrict__ b1,
                            uint32_t* __restrict__ Ahi, uint32_t* __restrict__ Alo) {
    int idx = blockIdx.x * blockDim.x + threadIdx.x;
    if (idx >= NNODES * NPAIRS) return;
    int n = idx >> 6;
    int p = idx & 63;
    int j0 = 2 * p;
    float x0 = nodes[n * 8 + off];
    float x1 = nodes[n * 8 + off + 1];
    float v0 = fmaxf(fmaf(x0, W1[j0 * 2],     fmaf(x1, W1[j0 * 2 + 1], b1[j0])),     0.0f);
    float v1 = fmaxf(fmaf(x0, W1[j0 * 2 + 2], fmaf(x1, W1[j0 * 2 + 3], b1[j0 + 1])), 0.0f);
    uint32_t hi, lo;
    split_pair(v0, v1, hi, lo);
    Ahi[idx] = hi;
    Alo[idx] = lo;
}

// ---------------- GEMM (init/meta/ctr2): interleaved W, LDS.64 B-frags --------
#define TC_THREADS 256
#define SW_STR     72
#define TC_SMEM    (2 * D * SW_STR * 4)
#define TC_GRID    296

__global__ void __launch_bounds__(TC_THREADS, 2)
gemm_tc_kernel(const uint32_t* __restrict__ Ahi, const uint32_t* __restrict__ Alo,
               const uint32_t* __restrict__ Whi, const uint32_t* __restrict__ Wlo,
               float* __restrict__ C, int nrows) {
    extern __shared__ uint32_t sm[];
    uint32_t* sWhi = sm;
    uint32_t* sWlo = sm + D * SW_STR;
    int tid = threadIdx.x;

    for (int idx = tid; idx < D * NPAIRS; idx += TC_THREADS) {
        int c = idx >> 6;
        int ip = idx & 63;
        sWhi[c * SW_STR + ip] = Whi[idx];
        sWlo[c * SW_STR + ip] = Wlo[idx];
    }
    __syncthreads();

    int wid  = tid >> 5;
    int lane = tid & 31;
    int rgrp = wid >> 1;
    int cgrp = wid & 1;
    int qr = lane >> 2;
    int qk = lane & 3;

    int ntiles = (nrows + 127) / 128;
    for (int tile = blockIdx.x; tile < ntiles; tile += gridDim.x) {
        int rbase = tile * 128 + rgrp * 32;
        int r00 = rbase + qr;
        int r01 = rbase + qr + 8;
        int r10 = rbase + 16 + qr;
        int r11 = rbase + 16 + qr + 8;
        bool v00 = r00 < nrows, v01 = r01 < nrows;
        bool v10 = r10 < nrows, v11 = r11 < nrows;

        float acc[2][8][4];
        #pragma unroll
        for (int s = 0; s < 2; s++)
            #pragma unroll
            for (int nt = 0; nt < 8; nt++)
                #pragma unroll
                for (int j = 0; j < 4; j++) acc[s][nt][j] = 0.0f;

        #pragma unroll
        for (int kt = 0; kt < 8; kt++) {
            int p0 = kt * 8 + qk;
            int p1 = p0 + 4;
            uint32_t ah0[4], al0[4], ah1[4], al1[4];
            ah0[0] = v00 ? Ahi[(long)r00 * NPAIRS + p0] : 0u;
            ah0[1] = v01 ? Ahi[(long)r01 * NPAIRS + p0] : 0u;
            ah0[2] = v00 ? Ahi[(long)r00 * NPAIRS + p1] : 0u;
            ah0[3] = v01 ? Ahi[(long)r01 * NPAIRS + p1] : 0u;
            al0[0] = v00 ? Alo[(long)r00 * NPAIRS + p0] : 0u;
            al0[1] = v01 ? Alo[(long)r01 * NPAIRS + p0] : 0u;
            al0[2] = v00 ? Alo[(long)r00 * NPAIRS + p1] : 0u;
            al0[3] = v01 ? Alo[(long)r01 * NPAIRS + p1] : 0u;
            ah1[0] = v10 ? Ahi[(long)r10 * NPAIRS + p0] : 0u;
            ah1[1] = v11 ? Ahi[(long)r11 * NPAIRS + p0] : 0u;
            ah1[2] = v10 ? Ahi[(long)r10 * NPAIRS + p1] : 0u;
            ah1[3] = v11 ? Ahi[(long)r11 * NPAIRS + p1] : 0u;
            al1[0] = v10 ? Alo[(long)r10 * NPAIRS + p0] : 0u;
            al1[1] = v11 ? Alo[(long)r11 * NPAIRS + p0] : 0u;
            al1[2] = v10 ? Alo[(long)r10 * NPAIRS + p1] : 0u;
            al1[3] = v11 ? Alo[(long)r11 * NPAIRS + p1] : 0u;

            #pragma unroll
            for (int nt = 0; nt < 8; nt++) {
                int n = cgrp * 64 + nt * 8 + qr;
                int o = n * SW_STR + kt * 8 + 2 * qk;
                uint2 BH = *reinterpret_cast<const uint2*>(&sWhi[o]);
                uint2 BL = *reinterpret_cast<const uint2*>(&sWlo[o]);
                uint32_t bh[2] = { BH.x, BH.y };
                uint32_t bl[2] = { BL.x, BL.y };
                mma_bf16(acc[0][nt], ah0, bh);
                mma_bf16(acc[0][nt], al0, bh);
                mma_bf16(acc[0][nt], ah0, bl);
                mma_bf16(acc[1][nt], ah1, bh);
                mma_bf16(acc[1][nt], al1, bh);
                mma_bf16(acc[1][nt], ah1, bl);
            }
        }

        #pragma unroll
        for (int nt = 0; nt < 8; nt++) {
            int col = cgrp * 64 + nt * 8 + 2 * qk;
            if (v00) *reinterpret_cast<float2*>(C + (long)r00 * D + col) =
                         make_float2(acc[0][nt][0], acc[0][nt][1]);
            if (v01) *reinterpret_cast<float2*>(C + (long)r01 * D + col) =
                         make_float2(acc[0][nt][2], acc[0][nt][3]);
            if (v10) *reinterpret_cast<float2*>(C + (long)r10 * D + col) =
                         make_float2(acc[1][nt][0], acc[1][nt][1]);
            if (v11) *reinterpret_cast<float2*>(C + (long)r11 * D + col) =
                         make_float2(acc[1][nt][2], acc[1][nt][3]);
        }
    }
}

// ---------------- persistent fused message-passing layer ----------------
// grid=148, 512 thr (16 warps). Slots OUTER (W loaded once per block per slot,
// double-buffered via cp.async); tiles INNER (A frags from hot L2 per tile).
// Warp = 16 rows x 64 cols. Epilogue: stage to smem, CSR red.v4 scatter.
#define MPP_THREADS 512
#define MPP_GRID    148
#define WP_STR      72
#define W_TILE      (D * WP_STR)                 // 9216 words
#define STG_STR     72
#define MPP_SMEM    ((4 * W_TILE + 16 * 16 * STG_STR) * 4)   // 221184 B

__global__ void __launch_bounds__(MPP_THREADS, 1)
mp_p_kernel(const uint32_t* __restrict__ Ahi, const uint32_t* __restrict__ Alo,
            const uint32_t* __restrict__ Whi, const uint32_t* __restrict__ Wlo,
            int layer,
            const int* __restrict__ off, const int* __restrict__ deg,
            const int* __restrict__ dstA,
            float* __restrict__ tmp, int nrows) {
    extern __shared__ uint32_t sm[];
    float* stage = reinterpret_cast<float*>(sm + 4 * W_TILE);
    uint32_t sbase = smem_u32(sm);

    int tid  = threadIdx.x;
    int wid  = tid >> 5;
    int lane = tid & 31;
    int rg = wid >> 1;     // 0..7: 16-row group
    int ch = wid & 1;      // 0..1: 64-col half
    int qr = lane >> 2;
    int qk = lane & 3;

    auto slot_of = [&](int s) {
        return (s == 0) ? (3 + layer) : (7 + layer * NTYPES + s - 1);
    };
    auto cp_w = [&](int s, int b) {
        const uint32_t* wh = Whi + (long)slot_of(s) * D * NPAIRS;
        const uint32_t* wl = Wlo + (long)slot_of(s) * D * NPAIRS;
        uint32_t bh = sbase + (uint32_t)(2 * b)     * W_TILE * 4u;
        uint32_t bl = sbase + (uint32_t)(2 * b + 1) * W_TILE * 4u;
        for (int i = tid * 4; i < D * NPAIRS; i += MPP_THREADS * 4) {
            int c = i >> 6, ip = i & 63;
            uint32_t o = (uint32_t)(c * WP_STR + ip) * 4u;
            cp16(bh + o, wh + i);
            cp16(bl + o, wl + i);
        }
        asm volatile("cp.async.commit_group;" ::: "memory");
    };

    cp_w(0, 0);

    int ntiles = (nrows + 127) / 128;
    for (int s = 0; s < 15; s++) {
        asm volatile("cp.async.wait_group 0;" ::: "memory");
        __syncthreads();          // W[s] visible; all warps done with slot s-1
        if (s < 14) cp_w(s + 1, (s + 1) & 1);

        const uint32_t* sWhi = sm + (size_t)(2 * (s & 1))     * W_TILE;
        const uint32_t* sWlo = sm + (size_t)(2 * (s & 1) + 1) * W_TILE;
        int t = s - 1;

        for (int tile = blockIdx.x; tile < ntiles; tile += MPP_GRID) {
            int rb = tile * 128 + rg * 16;
            int r0 = rb + qr;
            int r1 = rb + qr + 8;
            bool v0 = r0 < nrows;
            bool v1 = r1 < nrows;

            float acc[8][4];
            #pragma unroll
            for (int nt = 0; nt < 8; nt++)
                #pragma unroll
                for (int j = 0; j < 4; j++) acc[nt][j] = 0.0f;

            #pragma unroll 2
            for (int kt = 0; kt < 8; kt++) {
                int p0 = kt * 8 + qk;
                int p1 = p0 + 4;
                uint32_t a_h[4], a_l[4];
                a_h[0] = v0 ? Ahi[(long)r0 * NPAIRS + p0] : 0u;
                a_h[1] = v1 ? Ahi[(long)r1 * NPAIRS + p0] : 0u;
                a_h[2] = v0 ? Ahi[(long)r0 * NPAIRS + p1] : 0u;
                a_h[3] = v1 ? Ahi[(long)r1 * NPAIRS + p1] : 0u;
                a_l[0] = v0 ? Alo[(long)r0 * NPAIRS + p0] : 0u;
                a_l[1] = v1 ? Alo[(long)r1 * NPAIRS + p0] : 0u;
                a_l[2] = v0 ? Alo[(long)r0 * NPAIRS + p1] : 0u;
                a_l[3] = v1 ? Alo[(long)r1 * NPAIRS + p1] : 0u;

                #pragma unroll
                for (int nt = 0; nt < 8; nt++) {
                    int n = ch * 64 + nt * 8 + qr;
                    int o = n * WP_STR + kt * 8 + 2 * qk;
                    uint2 BH = *reinterpret_cast<const uint2*>(&sWhi[o]);
                    uint2 BL = *reinterpret_cast<const uint2*>(&sWlo[o]);
                    uint32_t bh[2] = { BH.x, BH.y };
                    uint32_t bl[2] = { BL.x, BL.y };
                    mma_bf16(acc[nt], a_h, bh);
                    mma_bf16(acc[nt], a_l, bh);
                    mma_bf16(acc[nt], a_h, bl);
                }
            }

            // stage warp tile (16 rows x 64 local cols)
            float* st = stage + wid * (16 * STG_STR);
            #pragma unroll
            for (int nt = 0; nt < 8; nt++) {
                int c2 = nt * 8 + 2 * qk;
                *reinterpret_cast<float2*>(&st[qr * STG_STR + c2]) =
                    make_float2(acc[nt][0], acc[nt][1]);
                *reinterpret_cast<float2*>(&st[(qr + 8) * STG_STR + c2]) =
                    make_float2(acc[nt][2], acc[nt][3]);
            }
            __syncwarp();

            // scatter: 2 rows per pass (lane>>4 selects row), 64-col half
            int colg = ch * 64 + (lane & 15) * 4;
            #pragma unroll
            for (int rr = 0; rr < 16; rr += 2) {
                int lr  = rr + (lane >> 4);
                int row = rb + lr;
                float4 v = *reinterpret_cast<float4*>(&st[lr * STG_STR + (lane & 15) * 4]);
                if (row < nrows) {
                    if (s == 0) {
                        red_v4(tmp + (long)row * D + colg, v);
                    } else {
                        long key = (long)t * NNODES + row;
                        int o0 = __ldg(off + key);
                        int dg = __ldg(deg + key);
                        for (int e = 0; e < dg; e++) {
                            int d = __ldg(dstA + o0 + e);
                            red_v4(tmp + (long)d * D + colg, v);
                        }
                    }
                }
            }
            __syncwarp();   // stage reuse next tile
        }
    }
}

// ---------------- GroupNorm helpers ----------------
__device__ __forceinline__ float warp_sum(float v) {
    #pragma unroll
    for (int o = 16; o > 0; o >>= 1) v += __shfl_xor_sync(0xffffffffu, v, o);
    return v;
}
__device__ __forceinline__ void store_split4(uint32_t* Ahi, uint32_t* Alo,
                                             int row, int lane, float4 y) {
    uint32_t h0, l0, h1, l1;
    split_pair(y.x, y.y, h0, l0);
    split_pair(y.z, y.w, h1, l1);
    *reinterpret_cast<uint2*>(Ahi + (long)row * NPAIRS + lane * 2) = make_uint2(h0, h1);
    *reinterpret_cast<uint2*>(Alo + (long)row * NPAIRS + lane * 2) = make_uint2(l0, l1);
}

__global__ void gn_kernel(const float* __restrict__ in,
                          const float* __restrict__ g, const float* __restrict__ b,
                          const float* __restrict__ resid,
                          float* __restrict__ out1, float* __restrict__ out2,
                          uint32_t* __restrict__ Ahi, uint32_t* __restrict__ Alo,
                          float* __restrict__ zbuf,
                          int do_relu) {
    int warp = (blockIdx.x * blockDim.x + threadIdx.x) >> 5;
    int lane = threadIdx.x & 31;
    if (warp >= NNODES) return;
    const float4 x = *reinterpret_cast<const float4*>(in + (long)warp * D + lane * 4);
    float s  = x.x + x.y + x.z + x.w;
    float ss = x.x * x.x + x.y * x.y + x.z * x.z + x.w * x.w;
    s  = warp_sum(s);
    ss = warp_sum(ss);
    float m   = s * (1.0f / 128.0f);
    float var = ss * (1.0f / 128.0f) - m * m;
    float inv = rsqrtf(var + 1e-5f);
    float4 gg = *reinterpret_cast<const float4*>(g + lane * 4);
    float4 bb = *reinterpret_cast<const float4*>(b + lane * 4);
    float4 y;
    y.x = fmaf((x.x - m) * inv, gg.x, bb.x);
    y.y = fmaf((x.y - m) * inv, gg.y, bb.y);
    y.z = fmaf((x.z - m) * inv, gg.z, bb.z);
    y.w = fmaf((x.w - m) * inv, gg.w, bb.w);
    if (resid) {
        float4 r = *reinterpret_cast<const float4*>(resid + (long)warp * D + lane * 4);
        y.x += r.x; y.y += r.y; y.z += r.z; y.w += r.w;
    }
    if (do_relu) {
        y.x = fmaxf(y.x, 0.0f); y.y = fmaxf(y.y, 0.0f);
        y.z = fmaxf(y.z, 0.0f); y.w = fmaxf(y.w, 0.0f);
    }
    *reinterpret_cast<float4*>(out1 + (long)warp * D + lane * 4) = y;
    if (out2)
        *reinterpret_cast<float4*>(out2 + (long)warp * D + lane * 4) = y;
    if (Ahi) store_split4(Ahi, Alo, warp, lane, y);
    if (zbuf)
        *reinterpret_cast<float4*>(zbuf + (long)warp * D + lane * 4) =
            make_float4(0.f, 0.f, 0.f, 0.f);
}

__global__ void gn2_kernel(const float* __restrict__ inA,
                           const float* __restrict__ gA, const float* __restrict__ bA,
                           const float* __restrict__ inB,
                           const float* __restrict__ gB, const float* __restrict__ bB,
                           float* __restrict__ out,
                           uint32_t* __restrict__ Ahi, uint32_t* __restrict__ Alo) {
    int warp = (blockIdx.x * blockDim.x + threadIdx.x) >> 5;
    int lane = threadIdx.x & 31;
    if (warp >= NNODES) return;
    const float4 xa = *reinterpret_cast<const float4*>(inA + (long)warp * D + lane * 4);
    const float4 xb = *reinterpret_cast<const float4*>(inB + (long)warp * D + lane * 4);
    float sa  = xa.x + xa.y + xa.z + xa.w;
    float ssa = xa.x * xa.x + xa.y * xa.y + xa.z * xa.z + xa.w * xa.w;
    float sb  = xb.x + xb.y + xb.z + xb.w;
    float ssb = xb.x * xb.x + xb.y * xb.y + xb.z * xb.z + xb.w * xb.w;
    sa = warp_sum(sa); ssa = warp_sum(ssa);
    sb = warp_sum(sb); ssb = warp_sum(ssb);
    float ma = sa * (1.0f / 128.0f);
    float mb = sb * (1.0f / 128.0f);
    float ia = rsqrtf(ssa * (1.0f / 128.0f) - ma * ma + 1e-5f);
    float ib = rsqrtf(ssb * (1.0f / 128.0f) - mb * mb + 1e-5f);
    float4 ga4 = *reinterpret_cast<const float4*>(gA + lane * 4);
    float4 ba4 = *reinterpret_cast<const float4*>(bA + lane * 4);
    float4 gb4 = *reinterpret_cast<const float4*>(gB + lane * 4);
    float4 bb4 = *reinterpret_cast<const float4*>(bB + lane * 4);
    float4 y;
    y.x = fmaf((xa.x - ma) * ia, ga4.x, ba4.x) + fmaf((xb.x - mb) * ib, gb4.x, bb4.x);
    y.y = fmaf((xa.y - ma) * ia, ga4.y, ba4.y) + fmaf((xb.y - mb) * ib, gb4.y, bb4.y);
    y.z = fmaf((xa.z - ma) * ia, ga4.z, ba4.z) + fmaf((xb.z - mb) * ib, gb4.z, bb4.z);
    y.w = fmaf((xa.w - ma) * ia, ga4.w, ba4.w) + fmaf((xb.w - mb) * ib, gb4.w, bb4.w);
    y.x = fmaxf(y.x, 0.0f); y.y = fmaxf(y.y, 0.0f);
    y.z = fmaxf(y.z, 0.0f); y.w = fmaxf(y.w, 0.0f);
    *reinterpret_cast<float4*>(out + (long)warp * D + lane * 4) = y;
    store_split4(Ahi, Alo, warp, lane, y);
}

// ---------------- rank-4 update ----------------
__global__ void rank4_kernel(const float* __restrict__ nodes,
                             const float* __restrict__ metaW,
                             float* __restrict__ out) {
    int idx = blockIdx.x * blockDim.x + threadIdx.x;
    if (idx >= NNODES * D) return;
    int n = idx >> 7;
    int c = idx & 127;
    const float* wr = metaW + c * 132 + 128;
    const float* nd = nodes + n * 8 + 4;
    float s = fmaf(nd[0], wr[0], fmaf(nd[1], wr[1], fmaf(nd[2], wr[2], nd[3] * wr[3])));
    out[idx] += s;
}

// ---------------- final output ----------------
__global__ void copy_out_kernel(const float* __restrict__ feat,
                                const float* __restrict__ nodes,
                                float* __restrict__ out) {
    int idx = blockIdx.x * blockDim.x + threadIdx.x;
    const int F = NNODES * D;
    if (idx < F) {
        out[idx] = feat[idx];
    } else if (idx < F + NNODES * 2) {
        int j = idx - F;
        int n = j >> 1;
        int c = j & 1;
        out[idx] = nodes[n * 8 + c];
    }
}

// ---------------- host launcher ----------------
extern "C" void kernel_launch(void* const* d_in, const int* in_sizes, int n_in,
                              void* d_out, int out_size) {
    const float* nodes   = (const float*)d_in[0];
    const int*   indexes = (const int*)  d_in[1];
    const int*   mask    = (const int*)  d_in[2];
    const float* in1_W   = (const float*)d_in[3];
    const float* in1_b   = (const float*)d_in[4];
    const float* in2_W   = (const float*)d_in[5];
    const float* in_g    = (const float*)d_in[6];
    const float* in_bg   = (const float*)d_in[7];
    const float* seg1_W  = (const float*)d_in[8];
    const float* seg1_b  = (const float*)d_in[9];
    const float* seg2_W  = (const float*)d_in[10];
    const float* seg_g   = (const float*)d_in[11];
    const float* seg_bg  = (const float*)d_in[12];
    const float* meta_W  = (const float*)d_in[13];
    const float* meta_g  = (const float*)d_in[14];
    const float* meta_bg = (const float*)d_in[15];
    const float* ctr_W   = (const float*)d_in[16];
    const float* edge_W  = (const float*)d_in[17];
    const float* norm_g  = (const float*)d_in[18];
    const float* norm_bg = (const float*)d_in[19];
    const float* ctr2_W  = (const float*)d_in[20];
    const float* ctr2_g  = (const float*)d_in[21];
    const float* ctr2_bg = (const float*)d_in[22];
    float* out = (float*)d_out;

    float *feat, *res, *tmp;
    uint32_t *Whi, *Wlo, *Ahi, *Alo;
    int *deg, *off, *cur, *dstA, *bsum;
    cudaGetSymbolAddress((void**)&feat, g_feat);
    cudaGetSymbolAddress((void**)&res,  g_res);
    cudaGetSymbolAddress((void**)&tmp,  g_tmp);
    cudaGetSymbolAddress((void**)&Whi,  g_Whi);
    cudaGetSymbolAddress((void**)&Wlo,  g_Wlo);
    cudaGetSymbolAddress((void**)&Ahi,  g_Ahi);
    cudaGetSymbolAddress((void**)&Alo,  g_Alo);
    cudaGetSymbolAddress((void**)&deg,  g_deg);
    cudaGetSymbolAddress((void**)&off,  g_off);
    cudaGetSymbolAddress((void**)&cur,  g_cur);
    cudaGetSymbolAddress((void**)&dstA, g_dst);
    cudaGetSymbolAddress((void**)&bsum, g_bsum);
    float* Hbuf;
    cudaGetSymbolAddress((void**)&Hbuf, g_H);

    cudaFuncSetAttribute(gemm_tc_kernel,
                         cudaFuncAttributeMaxDynamicSharedMemorySize, TC_SMEM);
    cudaFuncSetAttribute(mp_p_kernel,
                         cudaFuncAttributeMaxDynamicSharedMemorySize, MPP_SMEM);

    const int lin_grid = (NNODES * NPAIRS + 255) / 256;
    const int gn_grid  = (NNODES * 32 + 255) / 256;
    const int sw_grid  = (NSLOTS * D * NPAIRS + 255) / 256;
    const int r4_grid  = (NNODES * D + 255) / 256;
    const int te_grid  = (NTYPES * NEDGES + 255) / 256;
    const int zn_grid  = (SCAN_N + 255) / 256;

    auto sWp = [&](int s) { return Whi + (long)s * D * NPAIRS; };
    auto sLp = [&](int s) { return Wlo + (long)s * D * NPAIRS; };

    // ---- CSR build ----
    zero_deg_kernel<<<zn_grid, 256>>>(deg);
    deg_kernel<<<te_grid, 256>>>(indexes, mask, deg);
    scan1_kernel<<<SCAN_NBLK, 256>>>(deg, off, bsum);
    scan2_kernel<<<1, 512>>>(bsum, SCAN_NBLK);
    scan3_kernel<<<zn_grid, 256>>>(off, bsum, cur);
    fill_kernel<<<te_grid, 256>>>(indexes, mask, cur, dstA);

    // ---- pre-split weights (interleaved) ----
    split_w_kernel<<<sw_grid, 256>>>(in2_W, seg2_W, meta_W, ctr_W, edge_W, ctr2_W,
                                     Whi, Wlo);

    // ---- init: input + seg branches ----
    lin1_kernel<<<lin_grid, 256>>>(nodes, 0, in1_W, in1_b, Ahi, Alo);
    gemm_tc_kernel<<<TC_GRID, TC_THREADS, TC_SMEM>>>(Ahi, Alo, sWp(0), sLp(0), Hbuf, NNODES);
    lin1_kernel<<<lin_grid, 256>>>(nodes, 2, seg1_W, seg1_b, Ahi, Alo);
    gemm_tc_kernel<<<TC_GRID, TC_THREADS, TC_SMEM>>>(Ahi, Alo, sWp(1), sLp(1), res, NNODES);
    gn2_kernel<<<gn_grid, 256>>>(Hbuf, in_g, in_bg, res, seg_g, seg_bg, feat, Ahi, Alo);

    // ---- meta ----
    gemm_tc_kernel<<<TC_GRID, TC_THREADS, TC_SMEM>>>(Ahi, Alo, sWp(2), sLp(2), tmp, NNODES);
    rank4_kernel<<<r4_grid, 256>>>(nodes, meta_W, tmp);
    gn_kernel<<<gn_grid, 256>>>(tmp, meta_g, meta_bg, nullptr, feat, res, Ahi, Alo, tmp, 1);

    // ---- 4 message-passing layers ----
    for (int i = 0; i < 4; i++) {
        mp_p_kernel<<<MPP_GRID, MPP_THREADS, MPP_SMEM>>>(Ahi, Alo, Whi, Wlo, i,
                                                         off, deg, dstA, tmp, NNODES);
        gn_kernel<<<gn_grid, 256>>>(tmp, norm_g + i * D, norm_bg + i * D,
                                    nullptr, feat, nullptr, Ahi, Alo, nullptr, 1);
        gemm_tc_kernel<<<TC_GRID, TC_THREADS, TC_SMEM>>>(
            Ahi, Alo, sWp(63 + i), sLp(63 + i), tmp, NNODES);
        gn_kernel<<<gn_grid, 256>>>(tmp, ctr2_g + i * D, ctr2_bg + i * D,
                                    res, feat, res, Ahi, Alo,
                                    (i < 3) ? tmp : nullptr, 1);
    }

    // ---- outputs ----
    int total = NNODES * D + NNODES * 2;
    copy_out_kernel<<<(total + 255) / 256, 256>>>(feat, nodes, out);
}

// round 11
// speedup vs baseline: 3.0848x; 1.0007x over previous
#include <cuda_runtime.h>
#include <cuda_bf16.h>
#include <math.h>
#include <stdint.h>

#define NNODES 100000
#define NEDGES 100000
#define D      128
#define NPAIRS 64
#define NTYPES 14
#define NSLOTS 67   // 0:in2 1:seg2 2:meta 3..6:ctr 7..62:edge 63..66:ctr2

#define SCAN_N   (NTYPES * NNODES)
#define SCAN_BLK 4096
#define SCAN_NBLK ((SCAN_N + SCAN_BLK - 1) / SCAN_BLK)

// ---------------- static device scratch ----------------
__device__ float    g_feat[NNODES * D];
__device__ float    g_res [NNODES * D];
__device__ float    g_tmp [NNODES * D];
__device__ uint32_t g_Ahi [NNODES * NPAIRS];
__device__ uint32_t g_Alo [NNODES * NPAIRS];
__device__ uint32_t g_Whi [NSLOTS * D * NPAIRS];   // pair-interleaved layout
__device__ uint32_t g_Wlo [NSLOTS * D * NPAIRS];
__device__ float    g_H  [NNODES * D];
__device__ int g_deg [SCAN_N];
__device__ int g_off [SCAN_N];
__device__ int g_cur [SCAN_N];
__device__ int g_dst [NTYPES * NEDGES];
__device__ int g_bsum[512];

// ---------------- generic helpers ----------------
__device__ __forceinline__ uint32_t pack_bf16x2(float e0, float e1) {
    uint32_t r;
    asm("cvt.rn.bf16x2.f32 %0, %1, %2;" : "=r"(r) : "f"(e1), "f"(e0));
    return r;
}
__device__ __forceinline__ void split_pair(float x0, float x1,
                                           uint32_t& hi, uint32_t& lo) {
    hi = pack_bf16x2(x0, x1);
    float h0 = __uint_as_float(hi << 16);
    float h1 = __uint_as_float(hi & 0xFFFF0000u);
    lo = pack_bf16x2(x0 - h0, x1 - h1);
}
__device__ __forceinline__ void mma_bf16(float* d, const uint32_t* a, const uint32_t* b) {
    asm volatile(
        "mma.sync.aligned.m16n8k16.row.col.f32.bf16.bf16.f32 "
        "{%0,%1,%2,%3}, {%4,%5,%6,%7}, {%8,%9}, {%0,%1,%2,%3};"
        : "+f"(d[0]), "+f"(d[1]), "+f"(d[2]), "+f"(d[3])
        : "r"(a[0]), "r"(a[1]), "r"(a[2]), "r"(a[3]), "r"(b[0]), "r"(b[1]));
}
__device__ __forceinline__ void red_v4(float* p, float4 v) {
    asm volatile("red.global.add.v4.f32 [%0], {%1, %2, %3, %4};"
                 :: "l"(p), "f"(v.x), "f"(v.y), "f"(v.z), "f"(v.w) : "memory");
}
__device__ __forceinline__ void cp16(uint32_t dst_smem, const void* src) {
    asm volatile("cp.async.ca.shared.global [%0], [%1], 16;" :: "r"(dst_smem), "l"(src));
}
__device__ __forceinline__ uint32_t smem_u32(const void* p) {
    uint32_t a;
    asm("{ .reg .u64 t; cvta.to.shared.u64 t, %1; cvt.u32.u64 %0, t; }" : "=r"(a) : "l"(p));
    return a;
}

// ---------------- CSR build ----------------
__global__ void zero_deg_kernel(int* deg) {
    int i = blockIdx.x * blockDim.x + threadIdx.x;
    if (i < SCAN_N) deg[i] = 0;
}
__global__ void deg_kernel(const int* __restrict__ indexes,
                           const int* __restrict__ mask, int* __restrict__ deg) {
    int idx = blockIdx.x * blockDim.x + threadIdx.x;
    if (idx >= NTYPES * NEDGES) return;
    int t = idx / NEDGES;
    int e = idx - t * NEDGES;
    if (e >= __ldg(mask + t)) return;
    int src = indexes[e * 28 + 2 * t + 1];
    atomicAdd(&deg[t * NNODES + src], 1);
}
__global__ void scan1_kernel(const int* __restrict__ deg, int* __restrict__ off,
                             int* __restrict__ bsum) {
    __shared__ int warp_tot[8];
    int b = blockIdx.x, tid = threadIdx.x;
    int base = b * SCAN_BLK + tid * 16;
    int v[16];
    int run = 0;
    #pragma unroll
    for (int i = 0; i < 16; i++) {
        int idx = base + i;
        int t = (idx < SCAN_N) ? deg[idx] : 0;
        v[i] = run;
        run += t;
    }
    int lane = tid & 31, w = tid >> 5;
    int x = run;
    #pragma unroll
    for (int o = 1; o < 32; o <<= 1) {
        int y = __shfl_up_sync(0xffffffffu, x, o);
        if (lane >= o) x += y;
    }
    if (lane == 31) warp_tot[w] = x;
    __syncthreads();
    int woff = 0;
    for (int i = 0; i < w; i++) woff += warp_tot[i];
    int excl = x - run + woff;
    #pragma unroll
    for (int i = 0; i < 16; i++)
        if (base + i < SCAN_N) off[base + i] = v[i] + excl;
    if (tid == 255) bsum[b] = excl + run;
}
__global__ void scan2_kernel(int* bsum, int n) {
    __shared__ int sm[512];
    int tid = threadIdx.x;
    int v = (tid < n) ? bsum[tid] : 0;
    sm[tid] = v;
    __syncthreads();
    for (int o = 1; o < 512; o <<= 1) {
        int t = (tid >= o) ? sm[tid - o] : 0;
        __syncthreads();
        sm[tid] += t;
        __syncthreads();
    }
    if (tid < n) bsum[tid] = sm[tid] - v;
}
__global__ void scan3_kernel(int* __restrict__ off, const int* __restrict__ bsum,
                             int* __restrict__ cur) {
    int i = blockIdx.x * blockDim.x + threadIdx.x;
    if (i >= SCAN_N) return;
    int o = off[i] + bsum[i / SCAN_BLK];
    off[i] = o;
    cur[i] = o;
}
__global__ void fill_kernel(const int* __restrict__ indexes,
                            const int* __restrict__ mask,
                            int* __restrict__ cur, int* __restrict__ dstA) {
    int idx = blockIdx.x * blockDim.x + threadIdx.x;
    if (idx >= NTYPES * NEDGES) return;
    int t = idx / NEDGES;
    int e = idx - t * NEDGES;
    if (e >= __ldg(mask + t)) return;
    int src = indexes[e * 28 + 2 * t + 1];
    int dst = indexes[e * 28 + 2 * t];
    int pos = atomicAdd(&cur[t * NNODES + src], 1);
    dstA[pos] = dst;
}

// ---------------- pre-split weights (PAIR-INTERLEAVED gmem layout) -------------
__global__ void split_w_kernel(const float* __restrict__ in2,
                               const float* __restrict__ seg2,
                               const float* __restrict__ meta,
                               const float* __restrict__ ctr,
                               const float* __restrict__ edge,
                               const float* __restrict__ ctr2,
                               uint32_t* __restrict__ Whi,
                               uint32_t* __restrict__ Wlo) {
    int idx = blockIdx.x * blockDim.x + threadIdx.x;
    if (idx >= NSLOTS * D * NPAIRS) return;
    int slot = idx / (D * NPAIRS);
    int r    = idx - slot * (D * NPAIRS);
    int c    = r >> 6;
    int ip   = r & 63;
    int g  = ip >> 3;
    int w  = ip & 7;
    int qk = w >> 1;
    int j  = w & 1;
    int p  = 8 * g + qk + 4 * j;
    int k0 = 2 * p;
    float x0, x1;
    if      (slot == 0) { x0 = in2 [c * D + k0]; x1 = in2 [c * D + k0 + 1]; }
    else if (slot == 1) { x0 = seg2[c * D + k0]; x1 = seg2[c * D + k0 + 1]; }
    else if (slot == 2) { x0 = meta[c * 132 + k0]; x1 = meta[c * 132 + k0 + 1]; }
    else if (slot < 7)  { const float* wm = ctr  + (long)(slot - 3)  * D * D;
                          x0 = wm[c * D + k0]; x1 = wm[c * D + k0 + 1]; }
    else if (slot < 63) { const float* wm = edge + (long)(slot - 7)  * D * D;
                          x0 = wm[c * D + k0]; x1 = wm[c * D + k0 + 1]; }
    else                { const float* wm = ctr2 + (long)(slot - 63) * D * D;
                          x0 = wm[c * D + k0]; x1 = wm[c * D + k0 + 1]; }
    uint32_t hi, lo;
    split_pair(x0, x1, hi, lo);
    Whi[idx] = hi;
    Wlo[idx] = lo;
}

// ---------------- lin1 ----------------
__global__ void lin1_kernel(const float* __restrict__ nodes, int off,
                            const float* __restrict__ W1, const float* __restrict__ b1,
                            uint32_t* __restrict__ Ahi, uint32_t* __restrict__ Alo) {
    int idx = blockIdx.x * blockDim.x + threadIdx.x;
    if (idx >= NNODES * NPAIRS) return;
    int n = idx >> 6;
    int p = idx & 63;
    int j0 = 2 * p;
    float x0 = nodes[n * 8 + off];
    float x1 = nodes[n * 8 + off + 1];
    float v0 = fmaxf(fmaf(x0, W1[j0 * 2],     fmaf(x1, W1[j0 * 2 + 1], b1[j0])),     0.0f);
    float v1 = fmaxf(fmaf(x0, W1[j0 * 2 + 2], fmaf(x1, W1[j0 * 2 + 3], b1[j0 + 1])), 0.0f);
    uint32_t hi, lo;
    split_pair(v0, v1, hi, lo);
    Ahi[idx] = hi;
    Alo[idx] = lo;
}

// ---------------- GEMM (init/meta/ctr2): interleaved W, LDS.64 B-frags --------
#define TC_THREADS 256
#define SW_STR     72
#define TC_SMEM    (2 * D * SW_STR * 4)
#define TC_GRID    296

__global__ void __launch_bounds__(TC_THREADS, 2)
gemm_tc_kernel(const uint32_t* __restrict__ Ahi, const uint32_t* __restrict__ Alo,
               const uint32_t* __restrict__ Whi, const uint32_t* __restrict__ Wlo,
               float* __restrict__ C, int nrows) {
    extern __shared__ uint32_t sm[];
    uint32_t* sWhi = sm;
    uint32_t* sWlo = sm + D * SW_STR;
    int tid = threadIdx.x;

    for (int idx = tid; idx < D * NPAIRS; idx += TC_THREADS) {
        int c = idx >> 6;
        int ip = idx & 63;
        sWhi[c * SW_STR + ip] = Whi[idx];
        sWlo[c * SW_STR + ip] = Wlo[idx];
    }
    __syncthreads();

    int wid  = tid >> 5;
    int lane = tid & 31;
    int rgrp = wid >> 1;
    int cgrp = wid & 1;
    int qr = lane >> 2;
    int qk = lane & 3;

    int ntiles = (nrows + 127) / 128;
    for (int tile = blockIdx.x; tile < ntiles; tile += gridDim.x) {
        int rbase = tile * 128 + rgrp * 32;
        int r00 = rbase + qr;
        int r01 = rbase + qr + 8;
        int r10 = rbase + 16 + qr;
        int r11 = rbase + 16 + qr + 8;
        bool v00 = r00 < nrows, v01 = r01 < nrows;
        bool v10 = r10 < nrows, v11 = r11 < nrows;

        float acc[2][8][4];
        #pragma unroll
        for (int s = 0; s < 2; s++)
            #pragma unroll
            for (int nt = 0; nt < 8; nt++)
                #pragma unroll
                for (int j = 0; j < 4; j++) acc[s][nt][j] = 0.0f;

        #pragma unroll
        for (int kt = 0; kt < 8; kt++) {
            int p0 = kt * 8 + qk;
            int p1 = p0 + 4;
            uint32_t ah0[4], al0[4], ah1[4], al1[4];
            ah0[0] = v00 ? Ahi[(long)r00 * NPAIRS + p0] : 0u;
            ah0[1] = v01 ? Ahi[(long)r01 * NPAIRS + p0] : 0u;
            ah0[2] = v00 ? Ahi[(long)r00 * NPAIRS + p1] : 0u;
            ah0[3] = v01 ? Ahi[(long)r01 * NPAIRS + p1] : 0u;
            al0[0] = v00 ? Alo[(long)r00 * NPAIRS + p0] : 0u;
            al0[1] = v01 ? Alo[(long)r01 * NPAIRS + p0] : 0u;
            al0[2] = v00 ? Alo[(long)r00 * NPAIRS + p1] : 0u;
            al0[3] = v01 ? Alo[(long)r01 * NPAIRS + p1] : 0u;
            ah1[0] = v10 ? Ahi[(long)r10 * NPAIRS + p0] : 0u;
            ah1[1] = v11 ? Ahi[(long)r11 * NPAIRS + p0] : 0u;
            ah1[2] = v10 ? Ahi[(long)r10 * NPAIRS + p1] : 0u;
            ah1[3] = v11 ? Ahi[(long)r11 * NPAIRS + p1] : 0u;
            al1[0] = v10 ? Alo[(long)r10 * NPAIRS + p0] : 0u;
            al1[1] = v11 ? Alo[(long)r11 * NPAIRS + p0] : 0u;
            al1[2] = v10 ? Alo[(long)r10 * NPAIRS + p1] : 0u;
            al1[3] = v11 ? Alo[(long)r11 * NPAIRS + p1] : 0u;

            #pragma unroll
            for (int nt = 0; nt < 8; nt++) {
                int n = cgrp * 64 + nt * 8 + qr;
                int o = n * SW_STR + kt * 8 + 2 * qk;
                uint2 BH = *reinterpret_cast<const uint2*>(&sWhi[o]);
                uint2 BL = *reinterpret_cast<const uint2*>(&sWlo[o]);
                uint32_t bh[2] = { BH.x, BH.y };
                uint32_t bl[2] = { BL.x, BL.y };
                mma_bf16(acc[0][nt], ah0, bh);
                mma_bf16(acc[0][nt], al0, bh);
                mma_bf16(acc[0][nt], ah0, bl);
                mma_bf16(acc[1][nt], ah1, bh);
                mma_bf16(acc[1][nt], al1, bh);
                mma_bf16(acc[1][nt], ah1, bl);
            }
        }

        #pragma unroll
        for (int nt = 0; nt < 8; nt++) {
            int col = cgrp * 64 + nt * 8 + 2 * qk;
            if (v00) *reinterpret_cast<float2*>(C + (long)r00 * D + col) =
                         make_float2(acc[0][nt][0], acc[0][nt][1]);
            if (v01) *reinterpret_cast<float2*>(C + (long)r01 * D + col) =
                         make_float2(acc[0][nt][2], acc[0][nt][3]);
            if (v10) *reinterpret_cast<float2*>(C + (long)r10 * D + col) =
                         make_float2(acc[1][nt][0], acc[1][nt][1]);
            if (v11) *reinterpret_cast<float2*>(C + (long)r11 * D + col) =
                         make_float2(acc[1][nt][2], acc[1][nt][3]);
        }
    }
}

// ---------------- persistent fused message-passing layer ----------------
// grid=148, 512 thr (16 warps). Slots OUTER, tiles INNER (block tile = 256 rows).
// Warp = 32 rows (2 strips) x 64 cols: B-frags reused across strips -> 6 MMA / 2 LDS.64.
// Epilogue: stage+scatter one 16-row strip at a time (keeps stage smem at 16 rows/warp).
#define MPP_THREADS 512
#define MPP_GRID    148
#define WP_STR      72
#define W_TILE      (D * WP_STR)                 // 9216 words
#define STG_STR     72
#define MPP_SMEM    ((4 * W_TILE + 16 * 16 * STG_STR) * 4)   // 221184 B

__global__ void __launch_bounds__(MPP_THREADS, 1)
mp_p_kernel(const uint32_t* __restrict__ Ahi, const uint32_t* __restrict__ Alo,
            const uint32_t* __restrict__ Whi, const uint32_t* __restrict__ Wlo,
            int layer,
            const int* __restrict__ off, const int* __restrict__ deg,
            const int* __restrict__ dstA,
            float* __restrict__ tmp, int nrows) {
    extern __shared__ uint32_t sm[];
    float* stage = reinterpret_cast<float*>(sm + 4 * W_TILE);
    uint32_t sbase = smem_u32(sm);

    int tid  = threadIdx.x;
    int wid  = tid >> 5;
    int lane = tid & 31;
    int rg = wid >> 1;     // 0..7: 32-row group
    int ch = wid & 1;      // 0..1: 64-col half
    int qr = lane >> 2;
    int qk = lane & 3;

    auto slot_of = [&](int s) {
        return (s == 0) ? (3 + layer) : (7 + layer * NTYPES + s - 1);
    };
    auto cp_w = [&](int s, int b) {
        const uint32_t* wh = Whi + (long)slot_of(s) * D * NPAIRS;
        const uint32_t* wl = Wlo + (long)slot_of(s) * D * NPAIRS;
        uint32_t bh = sbase + (uint32_t)(2 * b)     * W_TILE * 4u;
        uint32_t bl = sbase + (uint32_t)(2 * b + 1) * W_TILE * 4u;
        for (int i = tid * 4; i < D * NPAIRS; i += MPP_THREADS * 4) {
            int c = i >> 6, ip = i & 63;
            uint32_t o = (uint32_t)(c * WP_STR + ip) * 4u;
            cp16(bh + o, wh + i);
            cp16(bl + o, wl + i);
        }
        asm volatile("cp.async.commit_group;" ::: "memory");
    };

    cp_w(0, 0);

    int ntiles = (nrows + 255) / 256;
    for (int s = 0; s < 15; s++) {
        asm volatile("cp.async.wait_group 0;" ::: "memory");
        __syncthreads();          // W[s] visible; all warps done with slot s-1
        if (s < 14) cp_w(s + 1, (s + 1) & 1);

        const uint32_t* sWhi = sm + (size_t)(2 * (s & 1))     * W_TILE;
        const uint32_t* sWlo = sm + (size_t)(2 * (s & 1) + 1) * W_TILE;
        int t = s - 1;

        for (int tile = blockIdx.x; tile < ntiles; tile += MPP_GRID) {
            int rb = tile * 256 + rg * 32;
            int r00 = rb + qr;
            int r01 = rb + qr + 8;
            int r10 = rb + 16 + qr;
            int r11 = rb + 16 + qr + 8;
            bool v00 = r00 < nrows, v01 = r01 < nrows;
            bool v10 = r10 < nrows, v11 = r11 < nrows;

            float acc[2][8][4];
            #pragma unroll
            for (int s2 = 0; s2 < 2; s2++)
                #pragma unroll
                for (int nt = 0; nt < 8; nt++)
                    #pragma unroll
                    for (int j = 0; j < 4; j++) acc[s2][nt][j] = 0.0f;

            #pragma unroll 2
            for (int kt = 0; kt < 8; kt++) {
                int p0 = kt * 8 + qk;
                int p1 = p0 + 4;
                uint32_t ah0[4], al0[4], ah1[4], al1[4];
                ah0[0] = v00 ? Ahi[(long)r00 * NPAIRS + p0] : 0u;
                ah0[1] = v01 ? Ahi[(long)r01 * NPAIRS + p0] : 0u;
                ah0[2] = v00 ? Ahi[(long)r00 * NPAIRS + p1] : 0u;
                ah0[3] = v01 ? Ahi[(long)r01 * NPAIRS + p1] : 0u;
                al0[0] = v00 ? Alo[(long)r00 * NPAIRS + p0] : 0u;
                al0[1] = v01 ? Alo[(long)r01 * NPAIRS + p0] : 0u;
                al0[2] = v00 ? Alo[(long)r00 * NPAIRS + p1] : 0u;
                al0[3] = v01 ? Alo[(long)r01 * NPAIRS + p1] : 0u;
                ah1[0] = v10 ? Ahi[(long)r10 * NPAIRS + p0] : 0u;
                ah1[1] = v11 ? Ahi[(long)r11 * NPAIRS + p0] : 0u;
                ah1[2] = v10 ? Ahi[(long)r10 * NPAIRS + p1] : 0u;
                ah1[3] = v11 ? Ahi[(long)r11 * NPAIRS + p1] : 0u;
                al1[0] = v10 ? Alo[(long)r10 * NPAIRS + p0] : 0u;
                al1[1] = v11 ? Alo[(long)r11 * NPAIRS + p0] : 0u;
                al1[2] = v10 ? Alo[(long)r10 * NPAIRS + p1] : 0u;
                al1[3] = v11 ? Alo[(long)r11 * NPAIRS + p1] : 0u;

                #pragma unroll
                for (int nt = 0; nt < 8; nt++) {
                    int n = ch * 64 + nt * 8 + qr;
                    int o = n * WP_STR + kt * 8 + 2 * qk;
                    uint2 BH = *reinterpret_cast<const uint2*>(&sWhi[o]);
                    uint2 BL = *reinterpret_cast<const uint2*>(&sWlo[o]);
                    uint32_t bh[2] = { BH.x, BH.y };
                    uint32_t bl[2] = { BL.x, BL.y };
                    mma_bf16(acc[0][nt], ah0, bh);
                    mma_bf16(acc[0][nt], al0, bh);
                    mma_bf16(acc[0][nt], ah0, bl);
                    mma_bf16(acc[1][nt], ah1, bh);
                    mma_bf16(acc[1][nt], al1, bh);
                    mma_bf16(acc[1][nt], ah1, bl);
                }
            }

            // stage + scatter one 16-row strip at a time
            float* st = stage + wid * (16 * STG_STR);
            #pragma unroll
            for (int s2 = 0; s2 < 2; s2++) {
                #pragma unroll
                for (int nt = 0; nt < 8; nt++) {
                    int c2 = nt * 8 + 2 * qk;
                    *reinterpret_cast<float2*>(&st[qr * STG_STR + c2]) =
                        make_float2(acc[s2][nt][0], acc[s2][nt][1]);
                    *reinterpret_cast<float2*>(&st[(qr + 8) * STG_STR + c2]) =
                        make_float2(acc[s2][nt][2], acc[s2][nt][3]);
                }
                __syncwarp();

                int srow = rb + s2 * 16;
                int colg = ch * 64 + (lane & 15) * 4;
                #pragma unroll
                for (int rr = 0; rr < 16; rr += 2) {
                    int lr  = rr + (lane >> 4);
                    int row = srow + lr;
                    float4 v = *reinterpret_cast<float4*>(
                        &st[lr * STG_STR + (lane & 15) * 4]);
                    if (row < nrows) {
                        if (s == 0) {
                            red_v4(tmp + (long)row * D + colg, v);
                        } else {
                            long key = (long)t * NNODES + row;
                            int o0 = __ldg(off + key);
                            int dg = __ldg(deg + key);
                            for (int e = 0; e < dg; e++) {
                                int d = __ldg(dstA + o0 + e);
                                red_v4(tmp + (long)d * D + colg, v);
                            }
                        }
                    }
                }
                __syncwarp();   // stage reuse next strip / next tile
            }
        }
    }
}

// ---------------- GroupNorm helpers ----------------
__device__ __forceinline__ float warp_sum(float v) {
    #pragma unroll
    for (int o = 16; o > 0; o >>= 1) v += __shfl_xor_sync(0xffffffffu, v, o);
    return v;
}
__device__ __forceinline__ void store_split4(uint32_t* Ahi, uint32_t* Alo,
                                             int row, int lane, float4 y) {
    uint32_t h0, l0, h1, l1;
    split_pair(y.x, y.y, h0, l0);
    split_pair(y.z, y.w, h1, l1);
    *reinterpret_cast<uint2*>(Ahi + (long)row * NPAIRS + lane * 2) = make_uint2(h0, h1);
    *reinterpret_cast<uint2*>(Alo + (long)row * NPAIRS + lane * 2) = make_uint2(l0, l1);
}

__global__ void gn_kernel(const float* __restrict__ in,
                          const float* __restrict__ g, const float* __restrict__ b,
                          const float* __restrict__ resid,
                          float* __restrict__ out1, float* __restrict__ out2,
                          uint32_t* __restrict__ Ahi, uint32_t* __restrict__ Alo,
                          float* __restrict__ zbuf,
                          int do_relu) {
    int warp = (blockIdx.x * blockDim.x + threadIdx.x) >> 5;
    int lane = threadIdx.x & 31;
    if (warp >= NNODES) return;
    const float4 x = *reinterpret_cast<const float4*>(in + (long)warp * D + lane * 4);
    float s  = x.x + x.y + x.z + x.w;
    float ss = x.x * x.x + x.y * x.y + x.z * x.z + x.w * x.w;
    s  = warp_sum(s);
    ss = warp_sum(ss);
    float m   = s * (1.0f / 128.0f);
    float var = ss * (1.0f / 128.0f) - m * m;
    float inv = rsqrtf(var + 1e-5f);
    float4 gg = *reinterpret_cast<const float4*>(g + lane * 4);
    float4 bb = *reinterpret_cast<const float4*>(b + lane * 4);
    float4 y;
    y.x = fmaf((x.x - m) * inv, gg.x, bb.x);
    y.y = fmaf((x.y - m) * inv, gg.y, bb.y);
    y.z = fmaf((x.z - m) * inv, gg.z, bb.z);
    y.w = fmaf((x.w - m) * inv, gg.w, bb.w);
    if (resid) {
        float4 r = *reinterpret_cast<const float4*>(resid + (long)warp * D + lane * 4);
        y.x += r.x; y.y += r.y; y.z += r.z; y.w += r.w;
    }
    if (do_relu) {
        y.x = fmaxf(y.x, 0.0f); y.y = fmaxf(y.y, 0.0f);
        y.z = fmaxf(y.z, 0.0f); y.w = fmaxf(y.w, 0.0f);
    }
    *reinterpret_cast<float4*>(out1 + (long)warp * D + lane * 4) = y;
    if (out2)
        *reinterpret_cast<float4*>(out2 + (long)warp * D + lane * 4) = y;
    if (Ahi) store_split4(Ahi, Alo, warp, lane, y);
    if (zbuf)
        *reinterpret_cast<float4*>(zbuf + (long)warp * D + lane * 4) =
            make_float4(0.f, 0.f, 0.f, 0.f);
}

__global__ void gn2_kernel(const float* __restrict__ inA,
                           const float* __restrict__ gA, const float* __restrict__ bA,
                           const float* __restrict__ inB,
                           const float* __restrict__ gB, const float* __restrict__ bB,
                           float* __restrict__ out,
                           uint32_t* __restrict__ Ahi, uint32_t* __restrict__ Alo) {
    int warp = (blockIdx.x * blockDim.x + threadIdx.x) >> 5;
    int lane = threadIdx.x & 31;
    if (warp >= NNODES) return;
    const float4 xa = *reinterpret_cast<const float4*>(inA + (long)warp * D + lane * 4);
    const float4 xb = *reinterpret_cast<const float4*>(inB + (long)warp * D + lane * 4);
    float sa  = xa.x + xa.y + xa.z + xa.w;
    float ssa = xa.x * xa.x + xa.y * xa.y + xa.z * xa.z + xa.w * xa.w;
    float sb  = xb.x + xb.y + xb.z + xb.w;
    float ssb = xb.x * xb.x + xb.y * xb.y + xb.z * xb.z + xb.w * xb.w;
    sa = warp_sum(sa); ssa = warp_sum(ssa);
    sb = warp_sum(sb); ssb = warp_sum(ssb);
    float ma = sa * (1.0f / 128.0f);
    float mb = sb * (1.0f / 128.0f);
    float ia = rsqrtf(ssa * (1.0f / 128.0f) - ma * ma + 1e-5f);
    float ib = rsqrtf(ssb * (1.0f / 128.0f) - mb * mb + 1e-5f);
    float4 ga4 = *reinterpret_cast<const float4*>(gA + lane * 4);
    float4 ba4 = *reinterpret_cast<const float4*>(bA + lane * 4);
    float4 gb4 = *reinterpret_cast<const float4*>(gB + lane * 4);
    float4 bb4 = *reinterpret_cast<const float4*>(bB + lane * 4);
    float4 y;
    y.x = fmaf((xa.x - ma) * ia, ga4.x, ba4.x) + fmaf((xb.x - mb) * ib, gb4.x, bb4.x);
    y.y = fmaf((xa.y - ma) * ia, ga4.y, ba4.y) + fmaf((xb.y - mb) * ib, gb4.y, bb4.y);
    y.z = fmaf((xa.z - ma) * ia, ga4.z, ba4.z) + fmaf((xb.z - mb) * ib, gb4.z, bb4.z);
    y.w = fmaf((xa.w - ma) * ia, ga4.w, ba4.w) + fmaf((xb.w - mb) * ib, gb4.w, bb4.w);
    y.x = fmaxf(y.x, 0.0f); y.y = fmaxf(y.y, 0.0f);
    y.z = fmaxf(y.z, 0.0f); y.w = fmaxf(y.w, 0.0f);
    *reinterpret_cast<float4*>(out + (long)warp * D + lane * 4) = y;
    store_split4(Ahi, Alo, warp, lane, y);
}

// ---------------- rank-4 update ----------------
__global__ void rank4_kernel(const float* __restrict__ nodes,
                             const float* __restrict__ metaW,
                             float* __restrict__ out) {
    int idx = blockIdx.x * blockDim.x + threadIdx.x;
    if (idx >= NNODES * D) return;
    int n = idx >> 7;
    int c = idx & 127;
    const float* wr = metaW + c * 132 + 128;
    const float* nd = nodes + n * 8 + 4;
    float s = fmaf(nd[0], wr[0], fmaf(nd[1], wr[1], fmaf(nd[2], wr[2], nd[3] * wr[3])));
    out[idx] += s;
}

// ---------------- final output ----------------
__global__ void copy_out_kernel(const float* __restrict__ feat,
                                const float* __restrict__ nodes,
                                float* __restrict__ out) {
    int idx = blockIdx.x * blockDim.x + threadIdx.x;
    const int F = NNODES * D;
    if (idx < F) {
        out[idx] = feat[idx];
    } else if (idx < F + NNODES * 2) {
        int j = idx - F;
        int n = j >> 1;
        int c = j & 1;
        out[idx] = nodes[n * 8 + c];
    }
}

// ---------------- host launcher ----------------
extern "C" void kernel_launch(void* const* d_in, const int* in_sizes, int n_in,
                              void* d_out, int out_size) {
    const float* nodes   = (const float*)d_in[0];
    const int*   indexes = (const int*)  d_in[1];
    const int*   mask    = (const int*)  d_in[2];
    const float* in1_W   = (const float*)d_in[3];
    const float* in1_b   = (const float*)d_in[4];
    const float* in2_W   = (const float*)d_in[5];
    const float* in_g    = (const float*)d_in[6];
    const float* in_bg   = (const float*)d_in[7];
    const float* seg1_W  = (const float*)d_in[8];
    const float* seg1_b  = (const float*)d_in[9];
    const float* seg2_W  = (const float*)d_in[10];
    const float* seg_g   = (const float*)d_in[11];
    const float* seg_bg  = (const float*)d_in[12];
    const float* meta_W  = (const float*)d_in[13];
    const float* meta_g  = (const float*)d_in[14];
    const float* meta_bg = (const float*)d_in[15];
    const float* ctr_W   = (const float*)d_in[16];
    const float* edge_W  = (const float*)d_in[17];
    const float* norm_g  = (const float*)d_in[18];
    const float* norm_bg = (const float*)d_in[19];
    const float* ctr2_W  = (const float*)d_in[20];
    const float* ctr2_g  = (const float*)d_in[21];
    const float* ctr2_bg = (const float*)d_in[22];
    float* out = (float*)d_out;

    float *feat, *res, *tmp;
    uint32_t *Whi, *Wlo, *Ahi, *Alo;
    int *deg, *off, *cur, *dstA, *bsum;
    cudaGetSymbolAddress((void**)&feat, g_feat);
    cudaGetSymbolAddress((void**)&res,  g_res);
    cudaGetSymbolAddress((void**)&tmp,  g_tmp);
    cudaGetSymbolAddress((void**)&Whi,  g_Whi);
    cudaGetSymbolAddress((void**)&Wlo,  g_Wlo);
    cudaGetSymbolAddress((void**)&Ahi,  g_Ahi);
    cudaGetSymbolAddress((void**)&Alo,  g_Alo);
    cudaGetSymbolAddress((void**)&deg,  g_deg);
    cudaGetSymbolAddress((void**)&off,  g_off);
    cudaGetSymbolAddress((void**)&cur,  g_cur);
    cudaGetSymbolAddress((void**)&dstA, g_dst);
    cudaGetSymbolAddress((void**)&bsum, g_bsum);
    float* Hbuf;
    cudaGetSymbolAddress((void**)&Hbuf, g_H);

    cudaFuncSetAttribute(gemm_tc_kernel,
                         cudaFuncAttributeMaxDynamicSharedMemorySize, TC_SMEM);
    cudaFuncSetAttribute(mp_p_kernel,
                         cudaFuncAttributeMaxDynamicSharedMemorySize, MPP_SMEM);

    const int lin_grid = (NNODES * NPAIRS + 255) / 256;
    const int gn_grid  = (NNODES * 32 + 255) / 256;
    const int sw_grid  = (NSLOTS * D * NPAIRS + 255) / 256;
    const int r4_grid  = (NNODES * D + 255) / 256;
    const int te_grid  = (NTYPES * NEDGES + 255) / 256;
    const int zn_grid  = (SCAN_N + 255) / 256;

    auto sWp = [&](int s) { return Whi + (long)s * D * NPAIRS; };
    auto sLp = [&](int s) { return Wlo + (long)s * D * NPAIRS; };

    // ---- CSR build ----
    zero_deg_kernel<<<zn_grid, 256>>>(deg);
    deg_kernel<<<te_grid, 256>>>(indexes, mask, deg);
    scan1_kernel<<<SCAN_NBLK, 256>>>(deg, off, bsum);
    scan2_kernel<<<1, 512>>>(bsum, SCAN_NBLK);
    scan3_kernel<<<zn_grid, 256>>>(off, bsum, cur);
    fill_kernel<<<te_grid, 256>>>(indexes, mask, cur, dstA);

    // ---- pre-split weights (interleaved) ----
    split_w_kernel<<<sw_grid, 256>>>(in2_W, seg2_W, meta_W, ctr_W, edge_W, ctr2_W,
                                     Whi, Wlo);

    // ---- init: input + seg branches ----
    lin1_kernel<<<lin_grid, 256>>>(nodes, 0, in1_W, in1_b, Ahi, Alo);
    gemm_tc_kernel<<<TC_GRID, TC_THREADS, TC_SMEM>>>(Ahi, Alo, sWp(0), sLp(0), Hbuf, NNODES);
    lin1_kernel<<<lin_grid, 256>>>(nodes, 2, seg1_W, seg1_b, Ahi, Alo);
    gemm_tc_kernel<<<TC_GRID, TC_THREADS, TC_SMEM>>>(Ahi, Alo, sWp(1), sLp(1), res, NNODES);
    gn2_kernel<<<gn_grid, 256>>>(Hbuf, in_g, in_bg, res, seg_g, seg_bg, feat, Ahi, Alo);

    // ---- meta ----
    gemm_tc_kernel<<<TC_GRID, TC_THREADS, TC_SMEM>>>(Ahi, Alo, sWp(2), sLp(2), tmp, NNODES);
    rank4_kernel<<<r4_grid, 256>>>(nodes, meta_W, tmp);
    gn_kernel<<<gn_grid, 256>>>(tmp, meta_g, meta_bg, nullptr, feat, res, Ahi, Alo, tmp, 1);

    // ---- 4 message-passing layers ----
    for (int i = 0; i < 4; i++) {
        mp_p_kernel<<<MPP_GRID, MPP_THREADS, MPP_SMEM>>>(Ahi, Alo, Whi, Wlo, i,
                                                         off, deg, dstA, tmp, NNODES);
        gn_kernel<<<gn_grid, 256>>>(tmp, norm_g + i * D, norm_bg + i * D,
                                    nullptr, feat, nullptr, Ahi, Alo, nullptr, 1);
        gemm_tc_kernel<<<TC_GRID, TC_THREADS, TC_SMEM>>>(
            Ahi, Alo, sWp(63 + i), sLp(63 + i), tmp, NNODES);
        gn_kernel<<<gn_grid, 256>>>(tmp, ctr2_g + i * D, ctr2_bg + i * D,
                                    res, feat, res, Ahi, Alo,
                                    (i < 3) ? tmp : nullptr, 1);
    }

    // ---- outputs ----
    int total = NNODES * D + NNODES * 2;
    copy_out_kernel<<<(total + 255) / 256, 256>>>(feat, nodes, out);
}